// round 6
// baseline (speedup 1.0000x reference)
#include <cuda_runtime.h>
#include <cstddef>

// Problem constants (fixed shapes)
#define NROWS   131072          // B*T = 64*2048
#define CGROUPS 4
#define DSUB    128             // d = D/C
#define KCODES  128
#define DFULL   512

#define ROWS_PER_BLOCK 128
#define THREADS 256

#define XS_STRIDE 132           // floats; pad 4 -> float4-aligned rows
#define ED_STRIDE 130           // ull (8B dup-pairs) per code row = 1040B (16 mod 128 -> 2-way max)

typedef unsigned long long ull;

// smem layout (BYTE offsets)
#define OFFB_EDUP  0                                        // 128*130*8 = 133120
#define OFFB_XS    (KCODES * ED_STRIDE * 8)                 // 133120
#define OFFB_E2    (OFFB_XS + ROWS_PER_BLOCK * XS_STRIDE * 4)   // 200704
#define OFFB_X2    (OFFB_E2 + KCODES * 4)                   // 201216
#define OFFB_LOSS  (OFFB_X2 + ROWS_PER_BLOCK * 4)           // 201728
#define OFFB_BESTK (OFFB_LOSS + ROWS_PER_BLOCK * 4)         // 202240
#define OFFB_IDX   (OFFB_BESTK + ROWS_PER_BLOCK * 4)        // 202752
#define SMEM_BYTES (OFFB_IDX + ROWS_PER_BLOCK * 4)          // 203264

// ---- packed f32x2 helpers (sm_103a FFMA2 path) ----
__device__ __forceinline__ ull pack2(float a, float b) {
    ull r;
    asm("mov.b64 %0, {%1, %2};" : "=l"(r)
        : "r"(__float_as_uint(a)), "r"(__float_as_uint(b)));
    return r;
}
__device__ __forceinline__ void unpack2(ull v, float& lo, float& hi) {
    unsigned a, b;
    asm("mov.b64 {%0, %1}, %2;" : "=r"(a), "=r"(b) : "l"(v));
    lo = __uint_as_float(a);
    hi = __uint_as_float(b);
}
__device__ __forceinline__ void fma2(ull& d, ull a, ull b) {
    asm("fma.rn.f32x2 %0, %1, %2, %3;" : "=l"(d) : "l"(a), "l"(b), "l"(d));
}

// XLA-style warp row-reduction: strided partials in s, shfl_down tree, sum in lane 0.
__device__ __forceinline__ float xla_warp_tree(float s) {
    s += __shfl_down_sync(0xffffffffu, s, 16);
    s += __shfl_down_sync(0xffffffffu, s, 8);
    s += __shfl_down_sync(0xffffffffu, s, 4);
    s += __shfl_down_sync(0xffffffffu, s, 2);
    s += __shfl_down_sync(0xffffffffu, s, 1);
    return s;
}

__global__ __launch_bounds__(THREADS)
void pvq_kernel(const float* __restrict__ inp,
                const float* __restrict__ emb,
                float* __restrict__ out_q,
                float* __restrict__ out_idx,
                float* __restrict__ out_loss,
                int write_aux)
{
    extern __shared__ char smraw[];
    ull*   edup    = (ull*)(smraw + OFFB_EDUP);     // dup-pair embedding tile
    float* xs      = (float*)(smraw + OFFB_XS);
    float* e2s     = (float*)(smraw + OFFB_E2);
    float* x2s     = (float*)(smraw + OFFB_X2);
    float* lossacc = (float*)(smraw + OFFB_LOSS);
    int*   bestk   = (int*)(smraw + OFFB_BESTK);
    int*   idxacc  = (int*)(smraw + OFFB_IDX);

    const int t    = threadIdx.x;
    const int row0 = blockIdx.x * ROWS_PER_BLOCK;
    const int cg   = t & 15;   // code group (codes cg + 16*j)
    const int rg   = t >> 4;   // row group (rows rg*8 .. rg*8+7)
    const int lane = t & 31;
    const int warp = t >> 5;   // 8 warps

    if (t < ROWS_PER_BLOCK) { lossacc[t] = 0.0f; idxacc[t] = 0; }

    int powc = KCODES * KCODES * KCODES;   // 128^3, /128 per group

    for (int c = 0; c < CGROUPS; ++c) {
        // ---- stage embeddings group c into smem as dup-pairs ----
        {
            const float4* eg = (const float4*)(emb + (size_t)c * KCODES * DSUB);
            #pragma unroll
            for (int i = 0; i < (KCODES * DSUB / 4) / THREADS; ++i) {  // 16 iters
                int f4 = t + i * THREADS;
                int k  = f4 >> 5, d4 = f4 & 31;
                float4 v = eg[f4];
                float4* dst = (float4*)(edup + (size_t)k * ED_STRIDE + 4 * d4);
                dst[0] = make_float4(v.x, v.x, v.y, v.y);
                dst[1] = make_float4(v.z, v.z, v.w, v.w);
            }
        }
        // ---- stage x tile (row-major, float4, fully coalesced) ----
        {
            #pragma unroll
            for (int i = 0; i < (ROWS_PER_BLOCK * DSUB / 4) / THREADS; ++i) {  // 16
                int f4 = t + i * THREADS;
                int r  = f4 >> 5, d4 = f4 & 31;
                float4 v = *(const float4*)(inp + (size_t)(row0 + r) * DFULL
                                            + c * DSUB + 4 * d4);
                *(float4*)(xs + r * XS_STRIDE + 4 * d4) = v;
            }
        }
        // ---- e2[k]: XLA row-reduce order (lane-strided partials + shfl tree) ----
        {
            #pragma unroll
            for (int it = 0; it < KCODES / 8; ++it) {   // 16 k's per warp
                int k = warp * 16 + it;
                const float* er = emb + ((size_t)c * KCODES + k) * DSUB;
                float s = 0.0f;
                #pragma unroll
                for (int i = 0; i < 4; ++i) {
                    float v = er[lane + 32 * i];
                    s = fmaf(v, v, s);
                }
                s = xla_warp_tree(s);
                if (lane == 0) e2s[k] = s;
            }
        }
        __syncthreads();

        // ---- x2[r]: same XLA warp pattern, from smem tile ----
        {
            #pragma unroll
            for (int it = 0; it < ROWS_PER_BLOCK / 8; ++it) {  // 16 rows per warp
                int r = warp * 16 + it;
                const float* xr = xs + r * XS_STRIDE;
                float s = 0.0f;
                #pragma unroll
                for (int i = 0; i < 4; ++i) {
                    float v = xr[lane + 32 * i];
                    s = fmaf(v, v, s);
                }
                s = xla_warp_tree(s);
                if (lane == 0) x2s[r] = s;
            }
        }

        // ---- main GEMM: 8 rows (4 f32x2 pairs) x 8 codes per thread ----
        // Each (row,code) acc is a sequential fma chain over d ascending
        // (bit-identical to cuBLAS SIMT sgemm accumulation).
        ull acc[4][8];
        #pragma unroll
        for (int p = 0; p < 4; ++p)
            #pragma unroll
            for (int j = 0; j < 8; ++j) acc[p][j] = 0ull;

        const float* xbase = xs + (rg * 8) * XS_STRIDE;
        const ull*   ebase = edup + (size_t)cg * ED_STRIDE;

        #pragma unroll 4
        for (int ch = 0; ch < DSUB / 4; ++ch) {
            const int dd = ch * 4;
            // x operands: pack rows (2p, 2p+1) — register-pair placement, no ALU
            ull xp[4][4];
            #pragma unroll
            for (int p = 0; p < 4; ++p) {
                #pragma unroll
                for (int q = 0; q < 4; ++q)
                    xp[p][q] = pack2(xbase[(2 * p)     * XS_STRIDE + dd + q],
                                     xbase[(2 * p + 1) * XS_STRIDE + dd + q]);
            }
            #pragma unroll
            for (int j = 0; j < 8; ++j) {
                const ull* ej = ebase + (size_t)(16 * j) * ED_STRIDE + dd;
                ulonglong2 e01 = *(const ulonglong2*)(ej);      // dup(e[dd]), dup(e[dd+1])
                ulonglong2 e23 = *(const ulonglong2*)(ej + 2);  // dup(e[dd+2]), dup(e[dd+3])
                #pragma unroll
                for (int p = 0; p < 4; ++p) {
                    fma2(acc[p][j], xp[p][0], e01.x);
                    fma2(acc[p][j], xp[p][1], e01.y);
                    fma2(acc[p][j], xp[p][2], e23.x);
                    fma2(acc[p][j], xp[p][3], e23.y);
                }
            }
        }
        __syncthreads();   // x2s visible to all

        // ---- scores + argmin: tmp = f32(x2 + e2_k); s = f32(tmp - 2*dot) ----
        float e2r[8];
        #pragma unroll
        for (int j = 0; j < 8; ++j) e2r[j] = e2s[cg + 16 * j];

        #pragma unroll
        for (int p = 0; p < 4; ++p) {
            #pragma unroll
            for (int h = 0; h < 2; ++h) {
                int r = rg * 8 + 2 * p + h;
                float x2v = x2s[r];
                float bs = __int_as_float(0x7f800000);  // +inf
                int   bk = 0;
                #pragma unroll
                for (int j = 0; j < 8; ++j) {
                    float lo, hi;
                    unpack2(acc[p][j], lo, hi);
                    float dot = h ? hi : lo;
                    float tmp = x2v + e2r[j];          // f32 round
                    float s   = tmp - 2.0f * dot;      // 2*dot exact, one round
                    if (s < bs) { bs = s; bk = cg + 16 * j; }  // keeps smallest k
                }
                #pragma unroll
                for (int off = 8; off >= 1; off >>= 1) {
                    float os = __shfl_xor_sync(0xffffffffu, bs, off);
                    int   ok = __shfl_xor_sync(0xffffffffu, bk, off);
                    if (os < bs || (os == bs && ok < bk)) { bs = os; bk = ok; }
                }
                if (cg == 0) {
                    bestk[r]  = bk;
                    idxacc[r] += bk * powc;
                }
            }
        }
        __syncthreads();   // bestk visible

        // ---- epilogue: warp-per-row; gather code, quantized_sg, loss partial ----
        #pragma unroll
        for (int rr = 0; rr < ROWS_PER_BLOCK / 8; ++rr) {   // 16 rows per warp
            int r = warp * 16 + rr;
            int k = bestk[r];
            const ull* erow = edup + (size_t)k * ED_STRIDE;
            const float* xrow = xs + r * XS_STRIDE;
            float* qrow = out_q + (size_t)(row0 + r) * DFULL + c * DSUB;

            float part = 0.0f;
            #pragma unroll
            for (int m = 0; m < 4; ++m) {
                int dd = lane + 32 * m;
                float ev = *(const float*)(erow + dd);  // lower half of dup pair
                float xv = xrow[dd];
                float dlt = ev - xv;
                part = fmaf(dlt, dlt, part);
                qrow[dd] = xv + dlt;                    // x + (q - x), matches ref
            }
            #pragma unroll
            for (int off = 16; off >= 1; off >>= 1)
                part += __shfl_xor_sync(0xffffffffu, part, off);
            if (lane == 0) lossacc[r] += part;
        }
        powc >>= 7;  // /128
        __syncthreads();
    }

    if (write_aux && t < ROWS_PER_BLOCK) {
        int n = row0 + t;
        out_idx[n] = (float)idxacc[t];
        float d2 = lossacc[t];
        out_loss[n] = d2 + 0.25f * d2;   // q_latent + 0.25*e_latent
    }
}

extern "C" void kernel_launch(void* const* d_in, const int* in_sizes, int n_in,
                              void* d_out, int out_size) {
    const float* inp = (const float*)d_in[0];   // inputs (64,2048,512) f32
    const float* emb = (const float*)d_in[1];   // embeddings (4,128,128) f32
    float* out = (float*)d_out;

    const long long QN = (long long)NROWS * DFULL;
    int write_aux = ((long long)out_size >= QN + 2LL * NROWS) ? 1 : 0;
    float* out_q    = out;
    float* out_idx  = out + QN;
    float* out_loss = out + QN + NROWS;

    cudaFuncSetAttribute(pvq_kernel,
                         cudaFuncAttributeMaxDynamicSharedMemorySize, SMEM_BYTES);
    pvq_kernel<<<NROWS / ROWS_PER_BLOCK, THREADS, SMEM_BYTES>>>(
        inp, emb, out_q, out_idx, out_loss, write_aux);
}

// round 7
// speedup vs baseline: 1.3283x; 1.3283x over previous
#include <cuda_runtime.h>
#include <cstddef>

// Problem constants (fixed shapes)
#define NROWS   131072          // B*T = 64*2048
#define CGROUPS 4
#define DSUB    128             // d = D/C
#define KCODES  128
#define DFULL   512

#define ROWS_PER_BLOCK 128
#define THREADS 512

typedef unsigned long long ull;

#define XD_STRIDE 132           // ull per row of xdup   (1056 B, 16B aligned)
#define EP_STRIDE 130           // ull per pair-row      (1040 B; lane stride 16 mod 128)

// smem layout (BYTE offsets)
#define OFFB_XDUP  0                                       // 128*132*8 = 135168
#define OFFB_EPAIR (ROWS_PER_BLOCK * XD_STRIDE * 8)        // 135168
#define OFFB_E2    (OFFB_EPAIR + 64 * EP_STRIDE * 8)       // 201728
#define OFFB_X2    (OFFB_E2 + KCODES * 4)                  // 202240
#define OFFB_LOSS  (OFFB_X2 + ROWS_PER_BLOCK * 4)          // 202752
#define OFFB_BESTK (OFFB_LOSS + ROWS_PER_BLOCK * 4)        // 203264
#define OFFB_IDX   (OFFB_BESTK + ROWS_PER_BLOCK * 4)       // 203776
#define SMEM_BYTES (OFFB_IDX + ROWS_PER_BLOCK * 4)         // 204288

// ---- packed f32x2 helpers (sm_103a FFMA2 path) ----
__device__ __forceinline__ void unpack2(ull v, float& lo, float& hi) {
    unsigned a, b;
    asm("mov.b64 {%0, %1}, %2;" : "=r"(a), "=r"(b) : "l"(v));
    lo = __uint_as_float(a);
    hi = __uint_as_float(b);
}
__device__ __forceinline__ void fma2(ull& d, ull a, ull b) {
    asm("fma.rn.f32x2 %0, %1, %2, %3;" : "=l"(d) : "l"(a), "l"(b), "l"(d));
}

// XLA-style warp row-reduction: strided partials in s, shfl_down tree, sum in lane 0.
__device__ __forceinline__ float xla_warp_tree(float s) {
    s += __shfl_down_sync(0xffffffffu, s, 16);
    s += __shfl_down_sync(0xffffffffu, s, 8);
    s += __shfl_down_sync(0xffffffffu, s, 4);
    s += __shfl_down_sync(0xffffffffu, s, 2);
    s += __shfl_down_sync(0xffffffffu, s, 1);
    return s;
}

__global__ __launch_bounds__(THREADS)
void pvq_kernel(const float* __restrict__ inp,
                const float* __restrict__ emb,
                float* __restrict__ out_q,
                float* __restrict__ out_idx,
                float* __restrict__ out_loss,
                int write_aux)
{
    extern __shared__ char smraw[];
    ull*   xdup    = (ull*)(smraw + OFFB_XDUP);     // (x,x) dup pairs per row
    ull*   epair   = (ull*)(smraw + OFFB_EPAIR);    // (E[2p][d], E[2p+1][d]) pairs
    float* e2s     = (float*)(smraw + OFFB_E2);
    float* x2s     = (float*)(smraw + OFFB_X2);
    float* lossacc = (float*)(smraw + OFFB_LOSS);
    int*   bestk   = (int*)(smraw + OFFB_BESTK);
    int*   idxacc  = (int*)(smraw + OFFB_IDX);
    float* epf     = (float*)epair;                 // scalar view
    float* xdf     = (float*)xdup;                  // scalar view (even idx = value)

    const int t    = threadIdx.x;
    const int row0 = blockIdx.x * ROWS_PER_BLOCK;
    const int cg   = t & 15;   // code group: pairs pj = cg + 16*jj, jj=0..3
    const int rg   = t >> 4;   // row group: rows rg*4 .. rg*4+3 (0..31)
    const int lane = t & 31;
    const int warp = t >> 5;   // 16 warps

    if (t < ROWS_PER_BLOCK) { lossacc[t] = 0.0f; idxacc[t] = 0; }

    int powc = KCODES * KCODES * KCODES;   // 128^3, /128 per group

    for (int c = 0; c < CGROUPS; ++c) {
        // ---- stage embeddings group c as code-pair-interleaved tile ----
        {
            const float4* eg = (const float4*)(emb + (size_t)c * KCODES * DSUB);
            #pragma unroll
            for (int i = 0; i < (KCODES * DSUB / 4) / THREADS; ++i) {  // 8 iters
                int f4 = t + i * THREADS;
                int k  = f4 >> 5, d4 = f4 & 31;
                float4 v = eg[f4];
                // dest: epf[ ((k>>1)*EP_STRIDE + dd)*2 + (k&1) ]
                int base = ((k >> 1) * EP_STRIDE + 4 * d4) * 2 + (k & 1);
                epf[base + 0] = v.x;
                epf[base + 2] = v.y;
                epf[base + 4] = v.z;
                epf[base + 6] = v.w;
            }
        }
        // ---- stage x tile as dup pairs ----
        {
            #pragma unroll
            for (int i = 0; i < (ROWS_PER_BLOCK * DSUB / 4) / THREADS; ++i) {  // 8
                int f4 = t + i * THREADS;
                int r  = f4 >> 5, d4 = f4 & 31;
                float4 v = *(const float4*)(inp + (size_t)(row0 + r) * DFULL
                                            + c * DSUB + 4 * d4);
                float4* dst = (float4*)(xdup + (size_t)r * XD_STRIDE + 4 * d4);
                dst[0] = make_float4(v.x, v.x, v.y, v.y);
                dst[1] = make_float4(v.z, v.z, v.w, v.w);
            }
        }
        // ---- e2[k]: XLA row-reduce order (lane-strided partials + shfl tree) ----
        {
            #pragma unroll
            for (int it = 0; it < KCODES / 16; ++it) {   // 8 k's per warp
                int k = warp * 8 + it;
                const float* er = emb + ((size_t)c * KCODES + k) * DSUB;
                float s = 0.0f;
                #pragma unroll
                for (int i = 0; i < 4; ++i) {
                    float v = er[lane + 32 * i];
                    s = fmaf(v, v, s);
                }
                s = xla_warp_tree(s);
                if (lane == 0) e2s[k] = s;
            }
        }
        __syncthreads();

        // ---- x2[r]: same XLA warp pattern, from dup tile (even floats) ----
        {
            #pragma unroll
            for (int it = 0; it < ROWS_PER_BLOCK / 16; ++it) {  // 8 rows per warp
                int r = warp * 8 + it;
                const float* xr = xdf + (size_t)r * XD_STRIDE * 2;
                float s = 0.0f;
                #pragma unroll
                for (int i = 0; i < 4; ++i) {
                    float v = xr[2 * (lane + 32 * i)];
                    s = fmaf(v, v, s);
                }
                s = xla_warp_tree(s);
                if (lane == 0) x2s[r] = s;
            }
        }

        // ---- main GEMM: 4 rows x 8 codes (4 code-pairs) per thread ----
        // acc[r][jj] lanes = codes (2*(cg+16jj), 2*(cg+16jj)+1); each lane is a
        // sequential fma chain over d ascending (bit-identical to R4 kernel).
        ull acc[4][4];
        #pragma unroll
        for (int r = 0; r < 4; ++r)
            #pragma unroll
            for (int jj = 0; jj < 4; ++jj) acc[r][jj] = 0ull;

        const ull* xb = xdup + (size_t)(rg * 4) * XD_STRIDE;
        const ull* eb = epair + (size_t)cg * EP_STRIDE;

        #pragma unroll 4
        for (int ch = 0; ch < DSUB / 2; ++ch) {
            const int dd = ch * 2;
            ulonglong2 xv[4];
            #pragma unroll
            for (int r = 0; r < 4; ++r)
                xv[r] = *(const ulonglong2*)(xb + r * XD_STRIDE + dd);
            #pragma unroll
            for (int jj = 0; jj < 4; ++jj) {
                ulonglong2 ev = *(const ulonglong2*)(eb + jj * (16 * EP_STRIDE) + dd);
                #pragma unroll
                for (int r = 0; r < 4; ++r) {
                    fma2(acc[r][jj], xv[r].x, ev.x);   // d = dd
                    fma2(acc[r][jj], xv[r].y, ev.y);   // d = dd+1
                }
            }
        }
        __syncthreads();   // x2s visible to all

        // ---- scores + argmin: tmp = f32(x2 + e2_k); s = f32(tmp - 2*dot) ----
        #pragma unroll
        for (int r = 0; r < 4; ++r) {
            int rr = rg * 4 + r;
            float x2v = x2s[rr];
            float bs = __int_as_float(0x7f800000);  // +inf
            int   bk = 0;
            #pragma unroll
            for (int jj = 0; jj < 4; ++jj) {        // k ascending within thread
                int k0 = 2 * (cg + 16 * jj);
                float lo, hi;
                unpack2(acc[r][jj], lo, hi);
                float s0 = (x2v + e2s[k0])     - 2.0f * lo;
                float s1 = (x2v + e2s[k0 + 1]) - 2.0f * hi;
                if (s0 < bs) { bs = s0; bk = k0; }
                if (s1 < bs) { bs = s1; bk = k0 + 1; }
            }
            // reduce across the 16 cg-lanes (lanes 0-15 and 16-31 independently)
            #pragma unroll
            for (int off = 8; off >= 1; off >>= 1) {
                float os = __shfl_xor_sync(0xffffffffu, bs, off);
                int   ok = __shfl_xor_sync(0xffffffffu, bk, off);
                if (os < bs || (os == bs && ok < bk)) { bs = os; bk = ok; }
            }
            if (cg == 0) {
                bestk[rr]  = bk;
                idxacc[rr] += bk * powc;
            }
        }
        __syncthreads();   // bestk visible

        // ---- epilogue: warp-per-row; gather code, quantized_sg, loss partial ----
        #pragma unroll
        for (int rrr = 0; rrr < ROWS_PER_BLOCK / 16; ++rrr) {   // 8 rows per warp
            int r = warp * 8 + rrr;
            int k = bestk[r];
            const float* erow = epf + ((size_t)(k >> 1) * EP_STRIDE) * 2 + (k & 1);
            const float* xrow = xdf + (size_t)r * XD_STRIDE * 2;
            float* qrow = out_q + (size_t)(row0 + r) * DFULL + c * DSUB;

            float part = 0.0f;
            #pragma unroll
            for (int m = 0; m < 4; ++m) {
                int dd = lane + 32 * m;
                float ev = erow[2 * dd];
                float xv = xrow[2 * dd];
                float dlt = ev - xv;
                part = fmaf(dlt, dlt, part);
                qrow[dd] = xv + dlt;                    // x + (q - x), matches ref
            }
            #pragma unroll
            for (int off = 16; off >= 1; off >>= 1)
                part += __shfl_xor_sync(0xffffffffu, part, off);
            if (lane == 0) lossacc[r] += part;
        }
        powc >>= 7;  // /128
        __syncthreads();
    }

    if (write_aux && t < ROWS_PER_BLOCK) {
        int n = row0 + t;
        out_idx[n] = (float)idxacc[t];
        float d2 = lossacc[t];
        out_loss[n] = d2 + 0.25f * d2;   // q_latent + 0.25*e_latent
    }
}

extern "C" void kernel_launch(void* const* d_in, const int* in_sizes, int n_in,
                              void* d_out, int out_size) {
    const float* inp = (const float*)d_in[0];   // inputs (64,2048,512) f32
    const float* emb = (const float*)d_in[1];   // embeddings (4,128,128) f32
    float* out = (float*)d_out;

    const long long QN = (long long)NROWS * DFULL;
    int write_aux = ((long long)out_size >= QN + 2LL * NROWS) ? 1 : 0;
    float* out_q    = out;
    float* out_idx  = out + QN;
    float* out_loss = out + QN + NROWS;

    cudaFuncSetAttribute(pvq_kernel,
                         cudaFuncAttributeMaxDynamicSharedMemorySize, SMEM_BYTES);
    pvq_kernel<<<NROWS / ROWS_PER_BLOCK, THREADS, SMEM_BYTES>>>(
        inp, emb, out_q, out_idx, out_loss, write_aux);
}

// round 9
// speedup vs baseline: 1.4479x; 1.0900x over previous
#include <cuda_runtime.h>
#include <cstdint>
#include <cstddef>

// Problem constants (fixed shapes)
#define NROWS   131072          // B*T = 64*2048
#define CGROUPS 4
#define DSUB    128             // d = D/C
#define KCODES  128
#define DFULL   512

#define ROWS_PER_BLOCK 128
#define THREADS 512

typedef unsigned long long ull;

#define XD_STRIDE 132           // ull per row of xdup (1056 B)

// smem layout (BYTE offsets)
#define OFFB_XDUP  0                                       // 128*132*8 = 135168
#define OFFB_ET    (ROWS_PER_BLOCK * XD_STRIDE * 8)        // 135168 (+65536)
#define OFFB_E2    (OFFB_ET + DSUB * 64 * 8)               // 200704
#define OFFB_X2    (OFFB_E2 + KCODES * 4)                  // 201216
#define OFFB_LOSS  (OFFB_X2 + ROWS_PER_BLOCK * 4)          // 201728
#define OFFB_BESTK (OFFB_LOSS + ROWS_PER_BLOCK * 4)        // 202240
#define OFFB_IDX   (OFFB_BESTK + ROWS_PER_BLOCK * 4)       // 202752
#define SMEM_BYTES (OFFB_IDX + ROWS_PER_BLOCK * 4)         // 203264

// global scratch: transposed dup-pair embeddings + e2 (written by pre_kernel)
__device__ ull   et_g[CGROUPS][DSUB * 64];    // 256 KB
__device__ float e2_g[CGROUPS][KCODES];       // 2 KB

// ---- packed f32x2 helpers (sm_103a FFMA2 path) ----
__device__ __forceinline__ void unpack2(ull v, float& lo, float& hi) {
    unsigned a, b;
    asm("mov.b64 {%0, %1}, %2;" : "=r"(a), "=r"(b) : "l"(v));
    lo = __uint_as_float(a);
    hi = __uint_as_float(b);
}
__device__ __forceinline__ void fma2(ull& d, ull a, ull b) {
    asm("fma.rn.f32x2 %0, %1, %2, %3;" : "=l"(d) : "l"(a), "l"(b), "l"(d));
}
// XLA-style warp row-reduction: strided partials in s, shfl_down tree, sum in lane 0.
__device__ __forceinline__ float xla_warp_tree(float s) {
    s += __shfl_down_sync(0xffffffffu, s, 16);
    s += __shfl_down_sync(0xffffffffu, s, 8);
    s += __shfl_down_sync(0xffffffffu, s, 4);
    s += __shfl_down_sync(0xffffffffu, s, 2);
    s += __shfl_down_sync(0xffffffffu, s, 1);
    return s;
}

// ---- pre-kernel: build et_g (code-pair, d-major) and e2_g (XLA order) ----
__global__ __launch_bounds__(256)
void pre_kernel(const float* __restrict__ emb) {
    int b = blockIdx.x;
    if (b < 128) {
        // et: one thread per output pair (write-linear)
        int idx = b * 256 + threadIdx.x;            // 0 .. 32767
        int c = idx >> 13, rem = idx & 8191, d = rem >> 6, p = rem & 63;
        float lo = emb[((size_t)c * KCODES + 2 * p)     * DSUB + d];
        float hi = emb[((size_t)c * KCODES + 2 * p + 1) * DSUB + d];
        et_g[c][d * 64 + p] =
            (ull)__float_as_uint(lo) | ((ull)__float_as_uint(hi) << 32);
    } else {
        // e2: one warp per 4 codes, exact XLA reduce order
        int lane = threadIdx.x & 31;
        int w = (b - 128) * 8 + (threadIdx.x >> 5);   // 0..127
        #pragma unroll
        for (int kk = 0; kk < 4; ++kk) {
            int kidx = w * 4 + kk;                    // 0..511
            int c = kidx >> 7, k = kidx & 127;
            const float* er = emb + ((size_t)c * KCODES + k) * DSUB;
            float s = 0.0f;
            #pragma unroll
            for (int i = 0; i < 4; ++i) {
                float v = er[lane + 32 * i];
                s = fmaf(v, v, s);
            }
            s = xla_warp_tree(s);
            if (lane == 0) e2_g[c][k] = s;
        }
    }
}

__global__ __launch_bounds__(THREADS)
void pvq_kernel(const float* __restrict__ inp,
                const float* __restrict__ emb,
                float* __restrict__ out_q,
                float* __restrict__ out_idx,
                float* __restrict__ out_loss,
                int write_aux)
{
    extern __shared__ char smraw[];
    ull*   xdup    = (ull*)(smraw + OFFB_XDUP);     // (x,x) dup pairs per row
    ull*   et      = (ull*)(smraw + OFFB_ET);       // et[d][64] code-pairs
    float* e2s     = (float*)(smraw + OFFB_E2);
    float* x2s     = (float*)(smraw + OFFB_X2);
    float* lossacc = (float*)(smraw + OFFB_LOSS);
    int*   bestk   = (int*)(smraw + OFFB_BESTK);
    int*   idxacc  = (int*)(smraw + OFFB_IDX);
    float* xdf     = (float*)xdup;                  // scalar view (even idx = value)

    const int t    = threadIdx.x;
    const int row0 = blockIdx.x * ROWS_PER_BLOCK;
    const int cg   = t & 15;   // code group: pairs pj = cg + 16*jj, jj=0..3
    const int rg   = t >> 4;   // row group: rows rg*4 .. rg*4+3 (0..31)
    const int lane = t & 31;
    const int warp = t >> 5;   // 16 warps

    if (t < ROWS_PER_BLOCK) { lossacc[t] = 0.0f; idxacc[t] = 0; }

    int powc = KCODES * KCODES * KCODES;   // 128^3, /128 per group

    for (int c = 0; c < CGROUPS; ++c) {
        // ---- stage et tile: coalesced global -> contiguous smem copy ----
        {
            const float4* src = (const float4*)(et_g[c]);   // 4096 float4
            float4* dst = (float4*)et;
            #pragma unroll
            for (int i = 0; i < 4096 / THREADS; ++i)        // 8 iters
                dst[t + i * THREADS] = src[t + i * THREADS];
        }
        // ---- stage x tile as dup pairs ----
        {
            #pragma unroll
            for (int i = 0; i < (ROWS_PER_BLOCK * DSUB / 4) / THREADS; ++i) {  // 8
                int f4 = t + i * THREADS;
                int r  = f4 >> 5, d4 = f4 & 31;
                float4 v = *(const float4*)(inp + (size_t)(row0 + r) * DFULL
                                            + c * DSUB + 4 * d4);
                float4* dst = (float4*)(xdup + (size_t)r * XD_STRIDE + 4 * d4);
                dst[0] = make_float4(v.x, v.x, v.y, v.y);
                dst[1] = make_float4(v.z, v.z, v.w, v.w);
            }
        }
        // ---- e2[k]: copy precomputed (exact XLA values) ----
        if (t < KCODES) e2s[t] = e2_g[c][t];
        __syncthreads();

        // ---- x2[r]: XLA warp pattern, from dup tile (even floats) ----
        {
            #pragma unroll
            for (int it = 0; it < ROWS_PER_BLOCK / 16; ++it) {  // 8 rows per warp
                int r = warp * 8 + it;
                const float* xr = xdf + (size_t)r * XD_STRIDE * 2;
                float s = 0.0f;
                #pragma unroll
                for (int i = 0; i < 4; ++i) {
                    float v = xr[2 * (lane + 32 * i)];
                    s = fmaf(v, v, s);
                }
                s = xla_warp_tree(s);
                if (lane == 0) x2s[r] = s;
            }
        }

        // ---- main GEMM: 4 rows x 8 codes (4 code-pairs) per thread ----
        // acc[r][jj] lanes = codes (2*(cg+16jj), 2*(cg+16jj)+1); each lane is a
        // sequential fma chain over d ascending (bit-identical to R7 kernel).
        ull acc[4][4];
        #pragma unroll
        for (int r = 0; r < 4; ++r)
            #pragma unroll
            for (int jj = 0; jj < 4; ++jj) acc[r][jj] = 0ull;

        const ull* xb = xdup + (size_t)(rg * 4) * XD_STRIDE;
        const ull* eb = et + cg;

        #pragma unroll 4
        for (int ch = 0; ch < DSUB / 2; ++ch) {
            const int dd = ch * 2;
            ulonglong2 xv[4];
            #pragma unroll
            for (int r = 0; r < 4; ++r)
                xv[r] = *(const ulonglong2*)(xb + r * XD_STRIDE + dd);
            ull e0[4], e1[4];
            #pragma unroll
            for (int jj = 0; jj < 4; ++jj) {
                e0[jj] = eb[(size_t)dd * 64 + 16 * jj];         // contiguous lanes
                e1[jj] = eb[(size_t)(dd + 1) * 64 + 16 * jj];
            }
            #pragma unroll
            for (int jj = 0; jj < 4; ++jj)
                #pragma unroll
                for (int r = 0; r < 4; ++r)
                    fma2(acc[r][jj], xv[r].x, e0[jj]);          // d = dd
            #pragma unroll
            for (int jj = 0; jj < 4; ++jj)
                #pragma unroll
                for (int r = 0; r < 4; ++r)
                    fma2(acc[r][jj], xv[r].y, e1[jj]);          // d = dd+1
        }
        __syncthreads();   // x2s visible to all

        // ---- scores + argmin: tmp = f32(x2 + e2_k); s = f32(tmp - 2*dot) ----
        #pragma unroll
        for (int r = 0; r < 4; ++r) {
            int rr = rg * 4 + r;
            float x2v = x2s[rr];
            float bs = __int_as_float(0x7f800000);  // +inf
            int   bk = 0;
            #pragma unroll
            for (int jj = 0; jj < 4; ++jj) {        // k ascending within thread
                int k0 = 2 * (cg + 16 * jj);
                float lo, hi;
                unpack2(acc[r][jj], lo, hi);
                float s0 = (x2v + e2s[k0])     - 2.0f * lo;
                float s1 = (x2v + e2s[k0 + 1]) - 2.0f * hi;
                if (s0 < bs) { bs = s0; bk = k0; }
                if (s1 < bs) { bs = s1; bk = k0 + 1; }
            }
            // reduce across the 16 cg-lanes (lanes 0-15 and 16-31 independently)
            #pragma unroll
            for (int off = 8; off >= 1; off >>= 1) {
                float os = __shfl_xor_sync(0xffffffffu, bs, off);
                int   ok = __shfl_xor_sync(0xffffffffu, bk, off);
                if (os < bs || (os == bs && ok < bk)) { bs = os; bk = ok; }
            }
            if (cg == 0) {
                bestk[rr]  = bk;
                idxacc[rr] += bk * powc;
            }
        }
        __syncthreads();   // bestk visible

        // ---- epilogue: warp-per-row from GLOBAL (coalesced, L2-hot) ----
        #pragma unroll
        for (int rrr = 0; rrr < ROWS_PER_BLOCK / 16; ++rrr) {   // 8 rows per warp
            int r = warp * 8 + rrr;
            int k = bestk[r];
            const float* eg = emb + ((size_t)c * KCODES + k) * DSUB;
            const float* xg = inp + (size_t)(row0 + r) * DFULL + c * DSUB;
            float* qrow = out_q + (size_t)(row0 + r) * DFULL + c * DSUB;

            float part = 0.0f;
            #pragma unroll
            for (int m = 0; m < 4; ++m) {
                int dd = lane + 32 * m;
                float ev = eg[dd];
                float xv = xg[dd];
                float dlt = ev - xv;
                part = fmaf(dlt, dlt, part);
                qrow[dd] = xv + dlt;                    // x + (q - x), matches ref
            }
            #pragma unroll
            for (int off = 16; off >= 1; off >>= 1)
                part += __shfl_xor_sync(0xffffffffu, part, off);
            if (lane == 0) lossacc[r] += part;
        }
        powc >>= 7;  // /128
        __syncthreads();
    }

    if (write_aux && t < ROWS_PER_BLOCK) {
        int n = row0 + t;
        out_idx[n] = (float)idxacc[t];
        float d2 = lossacc[t];
        out_loss[n] = d2 + 0.25f * d2;   // q_latent + 0.25*e_latent
    }
}

extern "C" void kernel_launch(void* const* d_in, const int* in_sizes, int n_in,
                              void* d_out, int out_size) {
    const float* inp = (const float*)d_in[0];   // inputs (64,2048,512) f32
    const float* emb = (const float*)d_in[1];   // embeddings (4,128,128) f32
    float* out = (float*)d_out;

    const long long QN = (long long)NROWS * DFULL;
    int write_aux = ((long long)out_size >= QN + 2LL * NROWS) ? 1 : 0;
    float* out_q    = out;
    float* out_idx  = out + QN;
    float* out_loss = out + QN + NROWS;

    pre_kernel<<<144, 256>>>(emb);

    cudaFuncSetAttribute(pvq_kernel,
                         cudaFuncAttributeMaxDynamicSharedMemorySize, SMEM_BYTES);
    pvq_kernel<<<NROWS / ROWS_PER_BLOCK, THREADS, SMEM_BYTES>>>(
        inp, emb, out_q, out_idx, out_loss, write_aux);
}

// round 10
// speedup vs baseline: 1.5013x; 1.0369x over previous
#include <cuda_runtime.h>
#include <cstdint>
#include <cstddef>

// Problem constants (fixed shapes)
#define NROWS   131072          // B*T = 64*2048
#define CGROUPS 4
#define DSUB    128             // d = D/C
#define KCODES  128
#define DFULL   512

#define ROWS_PER_BLOCK 128
#define THREADS 256             // 8 warps; tile 8 rows x 8 codes per thread

typedef unsigned long long ull;

#define XD_STRIDE 132           // ull per row of xdup (1056 B)

// smem layout (BYTE offsets)
#define OFFB_XDUP  0                                       // 128*132*8 = 135168
#define OFFB_ET    (ROWS_PER_BLOCK * XD_STRIDE * 8)        // 135168 (+65536)
#define OFFB_E2    (OFFB_ET + DSUB * 64 * 8)               // 200704
#define OFFB_X2    (OFFB_E2 + KCODES * 4)                  // 201216
#define OFFB_LOSS  (OFFB_X2 + ROWS_PER_BLOCK * 4)          // 201728
#define OFFB_BESTK (OFFB_LOSS + ROWS_PER_BLOCK * 4)        // 202240
#define OFFB_IDX   (OFFB_BESTK + ROWS_PER_BLOCK * 4)       // 202752
#define SMEM_BYTES (OFFB_IDX + ROWS_PER_BLOCK * 4)         // 203264

// global scratch: transposed dup-pair embeddings + e2 (written by pre_kernel)
__device__ ull   et_g[CGROUPS][DSUB * 64];    // 256 KB
__device__ float e2_g[CGROUPS][KCODES];       // 2 KB

// ---- packed f32x2 helpers (sm_103a FFMA2 path) ----
__device__ __forceinline__ void unpack2(ull v, float& lo, float& hi) {
    unsigned a, b;
    asm("mov.b64 {%0, %1}, %2;" : "=r"(a), "=r"(b) : "l"(v));
    lo = __uint_as_float(a);
    hi = __uint_as_float(b);
}
__device__ __forceinline__ void fma2(ull& d, ull a, ull b) {
    asm("fma.rn.f32x2 %0, %1, %2, %3;" : "=l"(d) : "l"(a), "l"(b), "l"(d));
}
// XLA-style warp row-reduction: strided partials in s, shfl_down tree, sum in lane 0.
__device__ __forceinline__ float xla_warp_tree(float s) {
    s += __shfl_down_sync(0xffffffffu, s, 16);
    s += __shfl_down_sync(0xffffffffu, s, 8);
    s += __shfl_down_sync(0xffffffffu, s, 4);
    s += __shfl_down_sync(0xffffffffu, s, 2);
    s += __shfl_down_sync(0xffffffffu, s, 1);
    return s;
}

// ---- pre-kernel: build et_g (code-pair, d-major) and e2_g (XLA order) ----
__global__ __launch_bounds__(256)
void pre_kernel(const float* __restrict__ emb) {
    int b = blockIdx.x;
    if (b < 128) {
        // et: one thread per output pair (write-linear)
        int idx = b * 256 + threadIdx.x;            // 0 .. 32767
        int c = idx >> 13, rem = idx & 8191, d = rem >> 6, p = rem & 63;
        float lo = emb[((size_t)c * KCODES + 2 * p)     * DSUB + d];
        float hi = emb[((size_t)c * KCODES + 2 * p + 1) * DSUB + d];
        et_g[c][d * 64 + p] =
            (ull)__float_as_uint(lo) | ((ull)__float_as_uint(hi) << 32);
    } else {
        // e2: one warp per 4 codes, exact XLA reduce order
        int lane = threadIdx.x & 31;
        int w = (b - 128) * 8 + (threadIdx.x >> 5);   // 0..127
        #pragma unroll
        for (int kk = 0; kk < 4; ++kk) {
            int kidx = w * 4 + kk;                    // 0..511
            int c = kidx >> 7, k = kidx & 127;
            const float* er = emb + ((size_t)c * KCODES + k) * DSUB;
            float s = 0.0f;
            #pragma unroll
            for (int i = 0; i < 4; ++i) {
                float v = er[lane + 32 * i];
                s = fmaf(v, v, s);
            }
            s = xla_warp_tree(s);
            if (lane == 0) e2_g[c][k] = s;
        }
    }
}

__global__ __launch_bounds__(THREADS)
void pvq_kernel(const float* __restrict__ inp,
                const float* __restrict__ emb,
                float* __restrict__ out_q,
                float* __restrict__ out_idx,
                float* __restrict__ out_loss,
                int write_aux)
{
    extern __shared__ char smraw[];
    ull*   xdup    = (ull*)(smraw + OFFB_XDUP);     // (x,x) dup pairs per row
    ull*   et      = (ull*)(smraw + OFFB_ET);       // et[d][64] code-pairs
    float* e2s     = (float*)(smraw + OFFB_E2);
    float* x2s     = (float*)(smraw + OFFB_X2);
    float* lossacc = (float*)(smraw + OFFB_LOSS);
    int*   bestk   = (int*)(smraw + OFFB_BESTK);
    int*   idxacc  = (int*)(smraw + OFFB_IDX);
    float* xdf     = (float*)xdup;                  // scalar view (even idx = value)

    const int t    = threadIdx.x;
    const int row0 = blockIdx.x * ROWS_PER_BLOCK;
    const int cg   = t & 15;   // code group: pairs pj = cg + 16*jj, jj=0..3
    const int rg   = t >> 4;   // row group: rows rg*8 .. rg*8+7 (0..15)
    const int lane = t & 31;
    const int warp = t >> 5;   // 8 warps

    if (t < ROWS_PER_BLOCK) { lossacc[t] = 0.0f; idxacc[t] = 0; }

    int powc = KCODES * KCODES * KCODES;   // 128^3, /128 per group

    for (int c = 0; c < CGROUPS; ++c) {
        // ---- stage et tile: coalesced global -> contiguous smem copy ----
        {
            const float4* src = (const float4*)(et_g[c]);   // 4096 float4
            float4* dst = (float4*)et;
            #pragma unroll
            for (int i = 0; i < 4096 / THREADS; ++i)        // 16 iters
                dst[t + i * THREADS] = src[t + i * THREADS];
        }
        // ---- stage x tile as dup pairs ----
        {
            #pragma unroll
            for (int i = 0; i < (ROWS_PER_BLOCK * DSUB / 4) / THREADS; ++i) {  // 16
                int f4 = t + i * THREADS;
                int r  = f4 >> 5, d4 = f4 & 31;
                float4 v = *(const float4*)(inp + (size_t)(row0 + r) * DFULL
                                            + c * DSUB + 4 * d4);
                float4* dst = (float4*)(xdup + (size_t)r * XD_STRIDE + 4 * d4);
                dst[0] = make_float4(v.x, v.x, v.y, v.y);
                dst[1] = make_float4(v.z, v.z, v.w, v.w);
            }
        }
        // ---- e2[k]: copy precomputed (exact XLA values) ----
        if (t < KCODES) e2s[t] = e2_g[c][t];
        __syncthreads();

        // ---- x2[r]: XLA warp pattern, from dup tile (even floats) ----
        {
            #pragma unroll
            for (int it = 0; it < ROWS_PER_BLOCK / 8; ++it) {  // 16 rows per warp
                int r = warp * 16 + it;
                const float* xr = xdf + (size_t)r * XD_STRIDE * 2;
                float s = 0.0f;
                #pragma unroll
                for (int i = 0; i < 4; ++i) {
                    float v = xr[2 * (lane + 32 * i)];
                    s = fmaf(v, v, s);
                }
                s = xla_warp_tree(s);
                if (lane == 0) x2s[r] = s;
            }
        }

        // ---- main GEMM: 8 rows x 8 codes (4 code-pairs) per thread ----
        // acc[r][jj] lanes = codes (2*(cg+16jj), 2*(cg+16jj)+1); each lane is a
        // sequential fma chain over d ascending (bit-identical to R9 kernel).
        ull acc[8][4];
        #pragma unroll
        for (int r = 0; r < 8; ++r)
            #pragma unroll
            for (int jj = 0; jj < 4; ++jj) acc[r][jj] = 0ull;

        const ull* xb = xdup + (size_t)(rg * 8) * XD_STRIDE;
        const ull* eb = et + cg;

        #pragma unroll 2
        for (int ch = 0; ch < DSUB / 2; ++ch) {
            const int dd = ch * 2;
            ulonglong2 xv[8];
            #pragma unroll
            for (int r = 0; r < 8; ++r)
                xv[r] = *(const ulonglong2*)(xb + r * XD_STRIDE + dd);
            ull e0[4], e1[4];
            #pragma unroll
            for (int jj = 0; jj < 4; ++jj) {
                e0[jj] = eb[(size_t)dd * 64 + 16 * jj];         // contiguous lanes
                e1[jj] = eb[(size_t)(dd + 1) * 64 + 16 * jj];
            }
            #pragma unroll
            for (int jj = 0; jj < 4; ++jj)
                #pragma unroll
                for (int r = 0; r < 8; ++r)
                    fma2(acc[r][jj], xv[r].x, e0[jj]);          // d = dd
            #pragma unroll
            for (int jj = 0; jj < 4; ++jj)
                #pragma unroll
                for (int r = 0; r < 8; ++r)
                    fma2(acc[r][jj], xv[r].y, e1[jj]);          // d = dd+1
        }
        __syncthreads();   // x2s visible to all

        // ---- scores + argmin: tmp = f32(x2 + e2_k); s = f32(tmp - 2*dot) ----
        #pragma unroll
        for (int r = 0; r < 8; ++r) {
            int rr = rg * 8 + r;
            float x2v = x2s[rr];
            float bs = __int_as_float(0x7f800000);  // +inf
            int   bk = 0;
            #pragma unroll
            for (int jj = 0; jj < 4; ++jj) {        // k ascending within thread
                int k0 = 2 * (cg + 16 * jj);
                float lo, hi;
                unpack2(acc[r][jj], lo, hi);
                float s0 = (x2v + e2s[k0])     - 2.0f * lo;
                float s1 = (x2v + e2s[k0 + 1]) - 2.0f * hi;
                if (s0 < bs) { bs = s0; bk = k0; }
                if (s1 < bs) { bs = s1; bk = k0 + 1; }
            }
            // reduce across the 16 cg-lanes (lanes 0-15 and 16-31 independently)
            #pragma unroll
            for (int off = 8; off >= 1; off >>= 1) {
                float os = __shfl_xor_sync(0xffffffffu, bs, off);
                int   ok = __shfl_xor_sync(0xffffffffu, bk, off);
                if (os < bs || (os == bs && ok < bk)) { bs = os; bk = ok; }
            }
            if (cg == 0) {
                bestk[rr]  = bk;
                idxacc[rr] += bk * powc;
            }
        }
        __syncthreads();   // bestk visible

        // ---- epilogue: warp-per-row from GLOBAL (coalesced, L2-hot) ----
        #pragma unroll
        for (int rrr = 0; rrr < ROWS_PER_BLOCK / 8; ++rrr) {   // 16 rows per warp
            int r = warp * 16 + rrr;
            int k = bestk[r];
            const float* eg = emb + ((size_t)c * KCODES + k) * DSUB;
            const float* xg = inp + (size_t)(row0 + r) * DFULL + c * DSUB;
            float* qrow = out_q + (size_t)(row0 + r) * DFULL + c * DSUB;

            float part = 0.0f;
            #pragma unroll
            for (int m = 0; m < 4; ++m) {
                int dd = lane + 32 * m;
                float ev = eg[dd];
                float xv = xg[dd];
                float dlt = ev - xv;
                part = fmaf(dlt, dlt, part);
                qrow[dd] = xv + dlt;                    // x + (q - x), matches ref
            }
            #pragma unroll
            for (int off = 16; off >= 1; off >>= 1)
                part += __shfl_xor_sync(0xffffffffu, part, off);
            if (lane == 0) lossacc[r] += part;
        }
        powc >>= 7;  // /128
        __syncthreads();
    }

    if (write_aux && t < ROWS_PER_BLOCK) {
        int n = row0 + t;
        out_idx[n] = (float)idxacc[t];
        float d2 = lossacc[t];
        out_loss[n] = d2 + 0.25f * d2;   // q_latent + 0.25*e_latent
    }
}

extern "C" void kernel_launch(void* const* d_in, const int* in_sizes, int n_in,
                              void* d_out, int out_size) {
    const float* inp = (const float*)d_in[0];   // inputs (64,2048,512) f32
    const float* emb = (const float*)d_in[1];   // embeddings (4,128,128) f32
    float* out = (float*)d_out;

    const long long QN = (long long)NROWS * DFULL;
    int write_aux = ((long long)out_size >= QN + 2LL * NROWS) ? 1 : 0;
    float* out_q    = out;
    float* out_idx  = out + QN;
    float* out_loss = out + QN + NROWS;

    pre_kernel<<<144, 256>>>(emb);

    cudaFuncSetAttribute(pvq_kernel,
                         cudaFuncAttributeMaxDynamicSharedMemorySize, SMEM_BYTES);
    pvq_kernel<<<NROWS / ROWS_PER_BLOCK, THREADS, SMEM_BYTES>>>(
        inp, emb, out_q, out_idx, out_loss, write_aux);
}

// round 11
// speedup vs baseline: 1.5629x; 1.0411x over previous
#include <cuda_runtime.h>
#include <cstdint>
#include <cstddef>

// Problem constants (fixed shapes)
#define NROWS   131072          // B*T = 64*2048
#define CGROUPS 4
#define DSUB    128             // d = D/C
#define KCODES  128
#define DFULL   512

#define ROWS_PER_BLOCK 128
#define THREADS 256             // 8 warps; tile 8 rows x 8 codes per thread
#define TAU     0.05f           // near-tie threshold for exact recheck

typedef unsigned long long ull;

#define XS_STRIDE 132           // floats per x row (528 B: float4-aligned, 8B pairs ok)
#define ES_STRIDE 130           // floats per e row (520 B: lane bank-stride 2 -> conflict-free)

// smem layout (BYTE offsets)
#define OFFB_XS    0                                       // 128*132*4 = 67584
#define OFFB_ES    (ROWS_PER_BLOCK * XS_STRIDE * 4)        // 67584 (+66560)
#define OFFB_E2    (OFFB_ES + KCODES * ES_STRIDE * 4)      // 134144
#define OFFB_X2    (OFFB_E2 + KCODES * 4)                  // 134656
#define OFFB_LOSS  (OFFB_X2 + ROWS_PER_BLOCK * 4)          // 135168
#define OFFB_BESTK (OFFB_LOSS + ROWS_PER_BLOCK * 4)        // 135680
#define OFFB_IDX   (OFFB_BESTK + ROWS_PER_BLOCK * 4)       // 136192
#define OFFB_FLAGS (OFFB_IDX + ROWS_PER_BLOCK * 4)         // 136704
#define OFFB_NFLAG (OFFB_FLAGS + ROWS_PER_BLOCK * 4)       // 137216
#define SMEM_BYTES (OFFB_NFLAG + 16)                       // 137232

// global scratch: e2 (exact XLA order), written by pre_kernel
__device__ float e2_g[CGROUPS][KCODES];

// ---- packed f32x2 helpers (sm_103a FFMA2 path) ----
__device__ __forceinline__ void unpack2(ull v, float& lo, float& hi) {
    unsigned a, b;
    asm("mov.b64 {%0, %1}, %2;" : "=r"(a), "=r"(b) : "l"(v));
    lo = __uint_as_float(a);
    hi = __uint_as_float(b);
}
__device__ __forceinline__ void fma2(ull& d, ull a, ull b) {
    asm("fma.rn.f32x2 %0, %1, %2, %3;" : "=l"(d) : "l"(a), "l"(b), "l"(d));
}
// XLA-style warp row-reduction: strided partials in s, shfl_down tree, sum in lane 0.
__device__ __forceinline__ float xla_warp_tree(float s) {
    s += __shfl_down_sync(0xffffffffu, s, 16);
    s += __shfl_down_sync(0xffffffffu, s, 8);
    s += __shfl_down_sync(0xffffffffu, s, 4);
    s += __shfl_down_sync(0xffffffffu, s, 2);
    s += __shfl_down_sync(0xffffffffu, s, 1);
    return s;
}

// ---- pre-kernel: e2_g in exact XLA reduce order ----
__global__ __launch_bounds__(256)
void pre_kernel(const float* __restrict__ emb) {
    int lane = threadIdx.x & 31;
    int w = blockIdx.x * 8 + (threadIdx.x >> 5);      // 0..127
    #pragma unroll
    for (int kk = 0; kk < 4; ++kk) {
        int kidx = w * 4 + kk;                        // 0..511
        int c = kidx >> 7, k = kidx & 127;
        const float* er = emb + ((size_t)c * KCODES + k) * DSUB;
        float s = 0.0f;
        #pragma unroll
        for (int i = 0; i < 4; ++i) {
            float v = er[lane + 32 * i];
            s = fmaf(v, v, s);
        }
        s = xla_warp_tree(s);
        if (lane == 0) e2_g[c][k] = s;
    }
}

__global__ __launch_bounds__(THREADS)
void pvq_kernel(const float* __restrict__ inp,
                const float* __restrict__ emb,
                float* __restrict__ out_q,
                float* __restrict__ out_idx,
                float* __restrict__ out_loss,
                int write_aux)
{
    extern __shared__ char smraw[];
    float* xs      = (float*)(smraw + OFFB_XS);     // plain x [r][d], stride 132
    float* es      = (float*)(smraw + OFFB_ES);     // plain e [k][d], stride 130
    float* e2s     = (float*)(smraw + OFFB_E2);
    float* x2s     = (float*)(smraw + OFFB_X2);
    float* lossacc = (float*)(smraw + OFFB_LOSS);
    int*   bestk   = (int*)(smraw + OFFB_BESTK);
    int*   idxacc  = (int*)(smraw + OFFB_IDX);
    int*   flags   = (int*)(smraw + OFFB_FLAGS);
    int*   nflag   = (int*)(smraw + OFFB_NFLAG);

    const int t    = threadIdx.x;
    const int row0 = blockIdx.x * ROWS_PER_BLOCK;
    const int cg   = t & 15;   // code group: codes cg + 16*j, j=0..7
    const int rg   = t >> 4;   // row group: rows rg*8 .. rg*8+7 (0..15)
    const int lane = t & 31;
    const int warp = t >> 5;   // 8 warps

    if (t < ROWS_PER_BLOCK) { lossacc[t] = 0.0f; idxacc[t] = 0; }

    int powc = KCODES * KCODES * KCODES;   // 128^3, /128 per group

    for (int c = 0; c < CGROUPS; ++c) {
        // ---- stage x tile (plain, float4, coalesced) ----
        {
            #pragma unroll
            for (int i = 0; i < (ROWS_PER_BLOCK * DSUB / 4) / THREADS; ++i) {  // 16
                int f4 = t + i * THREADS;
                int r  = f4 >> 5, d4 = f4 & 31;
                float4 v = *(const float4*)(inp + (size_t)(row0 + r) * DFULL
                                            + c * DSUB + 4 * d4);
                *(float4*)(xs + r * XS_STRIDE + 4 * d4) = v;
            }
        }
        // ---- stage e tile (plain, float4 load -> 2x float2 store) ----
        {
            const float4* eg = (const float4*)(emb + (size_t)c * KCODES * DSUB);
            #pragma unroll
            for (int i = 0; i < (KCODES * DSUB / 4) / THREADS; ++i) {          // 16
                int f4 = t + i * THREADS;
                int k  = f4 >> 5, d4 = f4 & 31;
                float4 v = eg[f4];
                float* dst = es + k * ES_STRIDE + 4 * d4;
                *(float2*)(dst)     = make_float2(v.x, v.y);
                *(float2*)(dst + 2) = make_float2(v.z, v.w);
            }
        }
        // ---- e2[k]: precomputed exact XLA values ----
        if (t < KCODES) e2s[t] = e2_g[c][t];
        if (t == 0) *nflag = 0;
        __syncthreads();

        // ---- x2[r]: exact XLA warp pattern from smem ----
        {
            #pragma unroll
            for (int it = 0; it < ROWS_PER_BLOCK / 8; ++it) {  // 16 rows per warp
                int r = warp * 16 + it;
                const float* xr = xs + r * XS_STRIDE;
                float s = 0.0f;
                #pragma unroll
                for (int i = 0; i < 4; ++i) {
                    float v = xr[lane + 32 * i];
                    s = fmaf(v, v, s);
                }
                s = xla_warp_tree(s);
                if (lane == 0) x2s[r] = s;
            }
        }

        // ---- main GEMM: 8 rows x 8 codes per thread; FFMA2 lanes = (even d, odd d)
        //      partial sums of the SAME (row,code). Both operands are natural
        //      adjacent-d pairs -> plain LDS.64, no dup, no MOV. ----
        ull acc[8][8];
        #pragma unroll
        for (int r = 0; r < 8; ++r)
            #pragma unroll
            for (int j = 0; j < 8; ++j) acc[r][j] = 0ull;

        const float* xb = xs + (size_t)(rg * 8) * XS_STRIDE;
        const float* eb = es + (size_t)cg * ES_STRIDE;

        #pragma unroll 4
        for (int ch = 0; ch < DSUB / 2; ++ch) {
            const int dd = ch * 2;
            ull xv[8], ev[8];
            #pragma unroll
            for (int r = 0; r < 8; ++r)
                xv[r] = *(const ull*)(xb + r * XS_STRIDE + dd);
            #pragma unroll
            for (int j = 0; j < 8; ++j)
                ev[j] = *(const ull*)(eb + (size_t)j * 16 * ES_STRIDE + dd);
            #pragma unroll
            for (int j = 0; j < 8; ++j)
                #pragma unroll
                for (int r = 0; r < 8; ++r)
                    fma2(acc[r][j], xv[r], ev[j]);
        }
        __syncthreads();   // x2s visible to all

        // ---- approx scores + argmin with top-2 gap tracking ----
        #pragma unroll
        for (int r = 0; r < 8; ++r) {
            int rr = rg * 8 + r;
            float x2v = x2s[rr];
            float bs = __int_as_float(0x7f800000);   // +inf
            float bs2 = bs;
            int   bk = 0;
            #pragma unroll
            for (int j = 0; j < 8; ++j) {            // k ascending within thread
                int k = cg + 16 * j;
                float lo, hi;
                unpack2(acc[r][j], lo, hi);
                float dot = lo + hi;                 // split-order combine (approx)
                float s = (x2v + e2s[k]) - 2.0f * dot;
                if (s < bs) { bs2 = bs; bs = s; bk = k; }
                else if (s < bs2) { bs2 = s; }
            }
            // reduce across the 16 cg-lanes (both half-warps independently)
            #pragma unroll
            for (int off = 8; off >= 1; off >>= 1) {
                float os  = __shfl_xor_sync(0xffffffffu, bs, off);
                int   ok  = __shfl_xor_sync(0xffffffffu, bk, off);
                float os2 = __shfl_xor_sync(0xffffffffu, bs2, off);
                if (os < bs || (os == bs && ok < bk)) {
                    bs2 = fminf(bs, os2);
                    bs = os; bk = ok;
                } else {
                    bs2 = fminf(bs2, os);
                }
            }
            if (cg == 0) {
                bestk[rr] = bk;
                if (bs2 - bs < TAU) {                // ambiguous -> exact recheck
                    int pos = atomicAdd(nflag, 1);
                    flags[pos] = rr;
                }
            }
        }
        __syncthreads();

        // ---- exact recheck for flagged rows (rare): bit-exact reference math ----
        {
            int nf = *nflag;
            for (int i = warp; i < nf; i += 8) {
                int row = flags[i];
                const float* xr = xs + (size_t)row * XS_STRIDE;
                float x2v = x2s[row];
                float bs = __int_as_float(0x7f800000);
                int   bk = 0;
                #pragma unroll
                for (int kb = 0; kb < 4; ++kb) {
                    int k = kb * 32 + lane;
                    const float* er = es + (size_t)k * ES_STRIDE;
                    float dt = 0.0f;
                    for (int dd = 0; dd < DSUB; ++dd)
                        dt = fmaf(xr[dd], er[dd], dt);       // sequential, ascending
                    float sc = (x2v + e2s[k]) - 2.0f * dt;   // reference rounding
                    if (sc < bs) { bs = sc; bk = k; }        // lane ks ascending
                }
                #pragma unroll
                for (int off = 16; off >= 1; off >>= 1) {
                    float os = __shfl_xor_sync(0xffffffffu, bs, off);
                    int   ok = __shfl_xor_sync(0xffffffffu, bk, off);
                    if (os < bs || (os == bs && ok < bk)) { bs = os; bk = ok; }
                }
                if (lane == 0) bestk[row] = bk;
            }
        }
        __syncthreads();

        // ---- index accumulation + epilogue (quantized_sg, loss) from smem ----
        if (t < ROWS_PER_BLOCK) idxacc[t] += bestk[t] * powc;
        #pragma unroll
        for (int rrr = 0; rrr < ROWS_PER_BLOCK / 8; ++rrr) {   // 16 rows per warp
            int r = warp * 16 + rrr;
            int k = bestk[r];
            const float* er = es + (size_t)k * ES_STRIDE;
            const float* xr = xs + (size_t)r * XS_STRIDE;
            float* qrow = out_q + (size_t)(row0 + r) * DFULL + c * DSUB;

            float part = 0.0f;
            #pragma unroll
            for (int m = 0; m < 4; ++m) {
                int dd = lane + 32 * m;
                float ev = er[dd];
                float xv = xr[dd];
                float dlt = ev - xv;
                part = fmaf(dlt, dlt, part);
                qrow[dd] = xv + dlt;                    // x + (q - x), matches ref
            }
            #pragma unroll
            for (int off = 16; off >= 1; off >>= 1)
                part += __shfl_xor_sync(0xffffffffu, part, off);
            if (lane == 0) lossacc[r] += part;
        }
        powc >>= 7;  // /128
        __syncthreads();
    }

    if (write_aux && t < ROWS_PER_BLOCK) {
        int n = row0 + t;
        out_idx[n] = (float)idxacc[t];
        float d2 = lossacc[t];
        out_loss[n] = d2 + 0.25f * d2;   // q_latent + 0.25*e_latent
    }
}

extern "C" void kernel_launch(void* const* d_in, const int* in_sizes, int n_in,
                              void* d_out, int out_size) {
    const float* inp = (const float*)d_in[0];   // inputs (64,2048,512) f32
    const float* emb = (const float*)d_in[1];   // embeddings (4,128,128) f32
    float* out = (float*)d_out;

    const long long QN = (long long)NROWS * DFULL;
    int write_aux = ((long long)out_size >= QN + 2LL * NROWS) ? 1 : 0;
    float* out_q    = out;
    float* out_idx  = out + QN;
    float* out_loss = out + QN + NROWS;

    pre_kernel<<<16, 256>>>(emb);

    cudaFuncSetAttribute(pvq_kernel,
                         cudaFuncAttributeMaxDynamicSharedMemorySize, SMEM_BYTES);
    pvq_kernel<<<NROWS / ROWS_PER_BLOCK, THREADS, SMEM_BYTES>>>(
        inp, emb, out_q, out_idx, out_loss, write_aux);
}

// round 12
// speedup vs baseline: 2.6186x; 1.6755x over previous
#include <cuda_runtime.h>
#include <cuda_bf16.h>
#include <cstdint>
#include <cstddef>

// Problem constants (fixed shapes)
#define NROWS   131072          // B*T = 64*2048
#define CGROUPS 4
#define DSUB    128             // d = D/C
#define KCODES  128
#define DFULL   512

#define ROWS_PER_BLOCK 128
#define THREADS 256             // 8 warps; warp = 16 rows x 128 codes
#define TAU     0.05f           // near-tie threshold for exact recheck

// bf16 tile: 128 rows x 136 bf16 stride (272 B rows -> conflict-free ldmatrix)
#define TROW    136
#define TILE_B  (128 * TROW * 2)            // 34816

// smem layout (BYTE offsets)
#define OFF_XB1  0
#define OFF_XB2  (1 * TILE_B)
#define OFF_EB1  (2 * TILE_B)
#define OFF_EB2  (3 * TILE_B)
#define OFF_AUX  (4 * TILE_B)               // 139264
#define OFF_E2S   (OFF_AUX)                 // f32[128]
#define OFF_X2S   (OFF_AUX + 512)
#define OFF_LOSS  (OFF_AUX + 1024)
#define OFF_BESTK (OFF_AUX + 1536)
#define OFF_IDXA  (OFF_AUX + 2048)
#define OFF_FLAGS (OFF_AUX + 2560)
#define OFF_NFLAG (OFF_AUX + 3072)
#define SMEM_BYTES (OFF_AUX + 3088)

// global scratch: e2 (exact XLA order), written by pre_kernel
__device__ float e2_g[CGROUPS][KCODES];

// ---------------- helpers ----------------
__device__ __forceinline__ uint32_t smem_u32(const void* p) {
    uint32_t a;
    asm("{ .reg .u64 t; cvta.to.shared.u64 t, %1; cvt.u32.u64 %0, t; }"
        : "=r"(a) : "l"(p));
    return a;
}
__device__ __forceinline__ void ldmx4(uint32_t* r, uint32_t addr) {
    asm volatile("ldmatrix.sync.aligned.m8n8.x4.shared.b16 {%0,%1,%2,%3}, [%4];"
                 : "=r"(r[0]), "=r"(r[1]), "=r"(r[2]), "=r"(r[3]) : "r"(addr));
}
__device__ __forceinline__ void ldmx2(uint32_t* r, uint32_t addr) {
    asm volatile("ldmatrix.sync.aligned.m8n8.x2.shared.b16 {%0,%1}, [%2];"
                 : "=r"(r[0]), "=r"(r[1]) : "r"(addr));
}
__device__ __forceinline__ void mma_bf16(float* c, const uint32_t* a, const uint32_t* b) {
    asm volatile(
        "mma.sync.aligned.m16n8k16.row.col.f32.bf16.bf16.f32 "
        "{%0,%1,%2,%3}, {%4,%5,%6,%7}, {%8,%9}, {%0,%1,%2,%3};"
        : "+f"(c[0]), "+f"(c[1]), "+f"(c[2]), "+f"(c[3])
        : "r"(a[0]), "r"(a[1]), "r"(a[2]), "r"(a[3]), "r"(b[0]), "r"(b[1]));
}
// XLA-style warp row-reduction: strided partials in s, shfl_down tree, sum in lane 0.
__device__ __forceinline__ float xla_warp_tree(float s) {
    s += __shfl_down_sync(0xffffffffu, s, 16);
    s += __shfl_down_sync(0xffffffffu, s, 8);
    s += __shfl_down_sync(0xffffffffu, s, 4);
    s += __shfl_down_sync(0xffffffffu, s, 2);
    s += __shfl_down_sync(0xffffffffu, s, 1);
    return s;
}
__device__ __forceinline__ uint32_t bf2_pack(float a, float b) {
    __nv_bfloat162 p = __halves2bfloat162(__float2bfloat16_rn(a), __float2bfloat16_rn(b));
    return *(uint32_t*)&p;
}

// ---- pre-kernel: e2_g in exact XLA reduce order ----
__global__ __launch_bounds__(256)
void pre_kernel(const float* __restrict__ emb) {
    int lane = threadIdx.x & 31;
    int w = blockIdx.x * 8 + (threadIdx.x >> 5);      // 0..127
    #pragma unroll
    for (int kk = 0; kk < 4; ++kk) {
        int kidx = w * 4 + kk;                        // 0..511
        int c = kidx >> 7, k = kidx & 127;
        const float* er = emb + ((size_t)c * KCODES + k) * DSUB;
        float s = 0.0f;
        #pragma unroll
        for (int i = 0; i < 4; ++i) {
            float v = er[lane + 32 * i];
            s = fmaf(v, v, s);
        }
        s = xla_warp_tree(s);
        if (lane == 0) e2_g[c][k] = s;
    }
}

// stage a 128x128 f32 source into two bf16 split tiles (hi, lo residual)
__device__ __forceinline__ void stage_split(const float* __restrict__ src, int srcld,
                                            char* t1, char* t2, int t) {
    #pragma unroll
    for (int i = 0; i < 16; ++i) {
        int f4 = t + i * THREADS;
        int r = f4 >> 5, d4 = f4 & 31;
        float4 v = *(const float4*)(src + (size_t)r * srcld + 4 * d4);
        float h0 = __bfloat162float(__float2bfloat16_rn(v.x));
        float h1 = __bfloat162float(__float2bfloat16_rn(v.y));
        float h2 = __bfloat162float(__float2bfloat16_rn(v.z));
        float h3 = __bfloat162float(__float2bfloat16_rn(v.w));
        uint2 w1, w2;
        w1.x = bf2_pack(v.x, v.y);
        w1.y = bf2_pack(v.z, v.w);
        w2.x = bf2_pack(v.x - h0, v.y - h1);
        w2.y = bf2_pack(v.z - h2, v.w - h3);
        size_t off = (size_t)r * (TROW * 2) + 8 * d4;
        *(uint2*)(t1 + off) = w1;
        *(uint2*)(t2 + off) = w2;
    }
}

__global__ __launch_bounds__(THREADS)
void pvq_kernel(const float* __restrict__ inp,
                const float* __restrict__ emb,
                float* __restrict__ out_q,
                float* __restrict__ out_idx,
                float* __restrict__ out_loss,
                int write_aux)
{
    extern __shared__ char sm[];
    float* e2s     = (float*)(sm + OFF_E2S);
    float* x2s     = (float*)(sm + OFF_X2S);
    float* lossacc = (float*)(sm + OFF_LOSS);
    int*   bestk   = (int*)(sm + OFF_BESTK);
    int*   idxacc  = (int*)(sm + OFF_IDXA);
    int*   flags   = (int*)(sm + OFF_FLAGS);
    int*   nflag   = (int*)(sm + OFF_NFLAG);

    const uint32_t sb = smem_u32(sm);
    const int t    = threadIdx.x;
    const int lane = t & 31;
    const int warp = t >> 5;               // 8 warps
    const int row0 = blockIdx.x * ROWS_PER_BLOCK;

    // ldmatrix per-lane address components
    const int rA = (lane & 7) + ((lane >> 3) & 1) * 8;  // A row within 16
    const int cA = (lane >> 4);                          // A k-half (x16B)
    const uint32_t aOff = (uint32_t)(warp * 16 + rA) * (TROW * 2) + cA * 16;
    const int rB = lane & 7;
    const int hB = (lane >> 3) & 1;
    const uint32_t bOff = (uint32_t)rB * (TROW * 2) + hB * 16;

    if (t < ROWS_PER_BLOCK) { lossacc[t] = 0.0f; idxacc[t] = 0; }

    int powc = KCODES * KCODES * KCODES;   // 128^3, /128 per group

    for (int c = 0; c < CGROUPS; ++c) {
        // ---- stage bf16 split tiles ----
        stage_split(inp + (size_t)row0 * DFULL + c * DSUB, DFULL,
                    sm + OFF_XB1, sm + OFF_XB2, t);
        stage_split(emb + (size_t)c * KCODES * DSUB, DSUB,
                    sm + OFF_EB1, sm + OFF_EB2, t);
        if (t < KCODES) e2s[t] = e2_g[c][t];
        if (t == 0) *nflag = 0;
        __syncthreads();

        // ---- x2[r]: exact XLA warp pattern from GLOBAL (L2-hot) ----
        #pragma unroll
        for (int it = 0; it < ROWS_PER_BLOCK / 8; ++it) {   // 16 rows per warp
            int r = warp * 16 + it;
            const float* xr = inp + (size_t)(row0 + r) * DFULL + c * DSUB;
            float s = 0.0f;
            #pragma unroll
            for (int i = 0; i < 4; ++i) {
                float v = xr[lane + 32 * i];
                s = fmaf(v, v, s);
            }
            s = xla_warp_tree(s);
            if (lane == 0) x2s[r] = s;
        }

        // ---- HMMA GEMM: 3 split passes fused per k-step ----
        float acc[16][4];
        #pragma unroll
        for (int nt = 0; nt < 16; ++nt)
            #pragma unroll
            for (int j = 0; j < 4; ++j) acc[nt][j] = 0.0f;

        const uint32_t a1A = sb + OFF_XB1 + aOff;
        const uint32_t a2A = sb + OFF_XB2 + aOff;
        const uint32_t b1A = sb + OFF_EB1 + bOff;
        const uint32_t b2A = sb + OFF_EB2 + bOff;

        #pragma unroll
        for (int kk = 0; kk < 8; ++kk) {
            uint32_t ra1[4], ra2[4];
            ldmx4(ra1, a1A + kk * 32);
            ldmx4(ra2, a2A + kk * 32);
            #pragma unroll
            for (int nt = 0; nt < 16; ++nt) {
                uint32_t rb1[2], rb2[2];
                uint32_t bo = kk * 32 + nt * (8 * TROW * 2);
                ldmx2(rb1, b1A + bo);
                ldmx2(rb2, b2A + bo);
                mma_bf16(acc[nt], ra1, rb1);   // x1*e1
                mma_bf16(acc[nt], ra1, rb2);   // x1*e2
                mma_bf16(acc[nt], ra2, rb1);   // x2*e1
            }
        }
        __syncthreads();   // x2s visible

        // ---- approx scores + argmin (per-row, 4 lanes per row) ----
        {
            int q = lane & 3;                 // 2-col group
            int g = lane >> 2;                // row-in-16 group 0..7
            #pragma unroll
            for (int half = 0; half < 2; ++half) {
                int row = warp * 16 + g + 8 * half;
                float x2v = x2s[row];
                float bs = __int_as_float(0x7f800000), bs2 = bs;
                int   bk = 0;
                #pragma unroll
                for (int nt = 0; nt < 16; ++nt) {
                    int k0 = 8 * nt + 2 * q;
                    float s0 = (x2v + e2s[k0])     - 2.0f * acc[nt][2 * half + 0];
                    float s1 = (x2v + e2s[k0 + 1]) - 2.0f * acc[nt][2 * half + 1];
                    if (s0 < bs) { bs2 = bs; bs = s0; bk = k0; }
                    else if (s0 < bs2) { bs2 = s0; }
                    if (s1 < bs) { bs2 = bs; bs = s1; bk = k0 + 1; }
                    else if (s1 < bs2) { bs2 = s1; }
                }
                // reduce among the 4 lanes of this row (xor 1, 2 stay in quad)
                #pragma unroll
                for (int off = 1; off <= 2; off <<= 1) {
                    float os  = __shfl_xor_sync(0xffffffffu, bs, off);
                    int   ok  = __shfl_xor_sync(0xffffffffu, bk, off);
                    float os2 = __shfl_xor_sync(0xffffffffu, bs2, off);
                    if (os < bs || (os == bs && ok < bk)) {
                        bs2 = fminf(bs, os2);
                        bs = os; bk = ok;
                    } else {
                        bs2 = fminf(bs2, os);
                    }
                }
                if (q == 0) {
                    bestk[row] = bk;
                    if (bs2 - bs < TAU) {               // ambiguous
                        int pos = atomicAdd(nflag, 1);
                        flags[pos] = row;
                    }
                }
            }
        }
        __syncthreads();

        // ---- exact recheck for flagged rows (rare): bit-exact reference math ----
        {
            int nf = *nflag;
            for (int i = warp; i < nf; i += 8) {
                int row = flags[i];
                const float* xg = inp + (size_t)(row0 + row) * DFULL + c * DSUB;
                float x2v = x2s[row];
                float bs = __int_as_float(0x7f800000);
                int   bk = 0;
                #pragma unroll
                for (int kb = 0; kb < 4; ++kb) {
                    int k = kb * 32 + lane;
                    const float* eg = emb + ((size_t)c * KCODES + k) * DSUB;
                    float dt = 0.0f;
                    for (int dd = 0; dd < DSUB; ++dd)
                        dt = fmaf(xg[dd], eg[dd], dt);       // sequential, ascending
                    float sc = (x2v + e2s[k]) - 2.0f * dt;   // reference rounding
                    if (sc < bs) { bs = sc; bk = k; }        // lane ks ascending
                }
                #pragma unroll
                for (int off = 16; off >= 1; off >>= 1) {
                    float os = __shfl_xor_sync(0xffffffffu, bs, off);
                    int   ok = __shfl_xor_sync(0xffffffffu, bk, off);
                    if (os < bs || (os == bs && ok < bk)) { bs = os; bk = ok; }
                }
                if (lane == 0) bestk[row] = bk;
            }
        }
        __syncthreads();

        // ---- index accumulation + epilogue (quantized_sg, loss) from GLOBAL ----
        if (t < ROWS_PER_BLOCK) idxacc[t] += bestk[t] * powc;
        #pragma unroll
        for (int rr = 0; rr < ROWS_PER_BLOCK / 8; ++rr) {   // 16 rows per warp
            int r = warp * 16 + rr;
            int k = bestk[r];
            const float* eg = emb + ((size_t)c * KCODES + k) * DSUB;
            const float* xg = inp + (size_t)(row0 + r) * DFULL + c * DSUB;
            float* qrow = out_q + (size_t)(row0 + r) * DFULL + c * DSUB;

            float part = 0.0f;
            #pragma unroll
            for (int m = 0; m < 4; ++m) {
                int dd = lane + 32 * m;
                float ev = eg[dd];
                float xv = xg[dd];
                float dlt = ev - xv;
                part = fmaf(dlt, dlt, part);
                qrow[dd] = xv + dlt;                    // x + (q - x), matches ref
            }
            #pragma unroll
            for (int off = 16; off >= 1; off >>= 1)
                part += __shfl_xor_sync(0xffffffffu, part, off);
            if (lane == 0) lossacc[r] += part;
        }
        powc >>= 7;  // /128
        __syncthreads();
    }

    if (write_aux && t < ROWS_PER_BLOCK) {
        int n = row0 + t;
        out_idx[n] = (float)idxacc[t];
        float d2 = lossacc[t];
        out_loss[n] = d2 + 0.25f * d2;   // q_latent + 0.25*e_latent
    }
}

extern "C" void kernel_launch(void* const* d_in, const int* in_sizes, int n_in,
                              void* d_out, int out_size) {
    const float* inp = (const float*)d_in[0];   // inputs (64,2048,512) f32
    const float* emb = (const float*)d_in[1];   // embeddings (4,128,128) f32
    float* out = (float*)d_out;

    const long long QN = (long long)NROWS * DFULL;
    int write_aux = ((long long)out_size >= QN + 2LL * NROWS) ? 1 : 0;
    float* out_q    = out;
    float* out_idx  = out + QN;
    float* out_loss = out + QN + NROWS;

    pre_kernel<<<16, 256>>>(emb);

    cudaFuncSetAttribute(pvq_kernel,
                         cudaFuncAttributeMaxDynamicSharedMemorySize, SMEM_BYTES);
    pvq_kernel<<<NROWS / ROWS_PER_BLOCK, THREADS, SMEM_BYTES>>>(
        inp, emb, out_q, out_idx, out_loss, write_aux);
}

// round 14
// speedup vs baseline: 2.7625x; 1.0549x over previous
#include <cuda_runtime.h>
#include <cuda_bf16.h>
#include <cstdint>
#include <cstddef>

// Problem constants (fixed shapes)
#define NROWS   131072          // B*T = 64*2048
#define CGROUPS 4
#define DSUB    128             // d = D/C
#define KCODES  128
#define DFULL   512

#define ROWS_PER_BLOCK 64
#define THREADS 256             // 8 warps = 4 row-sets (16 rows) x 2 code-halves (64)
#define TAU     0.05f           // near-tie threshold for exact recheck

// bf16 tile rows: 136 bf16 stride (272 B) -> conflict-free ldmatrix
#define TROW    136
#define TROWB   (TROW * 2)                  // 272 bytes
#define XTILE_B (ROWS_PER_BLOCK * TROWB)    // 17408
#define ETILE_B (KCODES * TROWB)            // 34816

// smem layout (BYTE offsets)
#define OFF_XB1   0
#define OFF_XB2   (XTILE_B)                         // 17408
#define OFF_EB1   (2 * XTILE_B)                     // 34816
#define OFF_EB2   (2 * XTILE_B + ETILE_B)           // 69632
#define OFF_AUX   (2 * XTILE_B + 2 * ETILE_B)       // 104448
#define OFF_E2S   (OFF_AUX)                         // f32[128]
#define OFF_X2S   (OFF_AUX + 512)                   // f32[64]
#define OFF_LOSS  (OFF_AUX + 768)                   // f32[64]
#define OFF_BESTK (OFF_AUX + 1024)                  // int[64]
#define OFF_IDXA  (OFF_AUX + 1280)                  // int[64]
#define OFF_FLAGS (OFF_AUX + 1536)                  // int[64]
#define OFF_HBS   (OFF_AUX + 1792)                  // f32[64][2]
#define OFF_HBS2  (OFF_AUX + 2304)                  // f32[64][2]
#define OFF_HBK   (OFF_AUX + 2816)                  // int[64][2]
#define OFF_NFLAG (OFF_AUX + 3328)                  // int
#define SMEM_BYTES (OFF_AUX + 3344)                 // 107792 (< 113.5 KB -> 2 CTAs/SM)

// global scratch: e2 (exact XLA order), written by pre_kernel
__device__ float e2_g[CGROUPS][KCODES];

// ---------------- helpers ----------------
__device__ __forceinline__ uint32_t smem_u32(const void* p) {
    uint32_t a;
    asm("{ .reg .u64 t; cvta.to.shared.u64 t, %1; cvt.u32.u64 %0, t; }"
        : "=r"(a) : "l"(p));
    return a;
}
__device__ __forceinline__ void ldmx4(uint32_t* r, uint32_t addr) {
    asm volatile("ldmatrix.sync.aligned.m8n8.x4.shared.b16 {%0,%1,%2,%3}, [%4];"
                 : "=r"(r[0]), "=r"(r[1]), "=r"(r[2]), "=r"(r[3]) : "r"(addr));
}
__device__ __forceinline__ void mma_bf16(float* c, const uint32_t* a, const uint32_t* b) {
    asm volatile(
        "mma.sync.aligned.m16n8k16.row.col.f32.bf16.bf16.f32 "
        "{%0,%1,%2,%3}, {%4,%5,%6,%7}, {%8,%9}, {%0,%1,%2,%3};"
        : "+f"(c[0]), "+f"(c[1]), "+f"(c[2]), "+f"(c[3])
        : "r"(a[0]), "r"(a[1]), "r"(a[2]), "r"(a[3]), "r"(b[0]), "r"(b[1]));
}
// XLA-style warp row-reduction: strided partials in s, shfl_down tree, sum in lane 0.
__device__ __forceinline__ float xla_warp_tree(float s) {
    s += __shfl_down_sync(0xffffffffu, s, 16);
    s += __shfl_down_sync(0xffffffffu, s, 8);
    s += __shfl_down_sync(0xffffffffu, s, 4);
    s += __shfl_down_sync(0xffffffffu, s, 2);
    s += __shfl_down_sync(0xffffffffu, s, 1);
    return s;
}
__device__ __forceinline__ uint32_t bf2_pack(float a, float b) {
    __nv_bfloat162 p = __halves2bfloat162(__float2bfloat16_rn(a), __float2bfloat16_rn(b));
    return *(uint32_t*)&p;
}

// ---- pre-kernel: e2_g in exact XLA reduce order ----
__global__ __launch_bounds__(256)
void pre_kernel(const float* __restrict__ emb) {
    int lane = threadIdx.x & 31;
    int w = blockIdx.x * 8 + (threadIdx.x >> 5);      // 0..127
    #pragma unroll
    for (int kk = 0; kk < 4; ++kk) {
        int kidx = w * 4 + kk;                        // 0..511
        int c = kidx >> 7, k = kidx & 127;
        const float* er = emb + ((size_t)c * KCODES + k) * DSUB;
        float s = 0.0f;
        #pragma unroll
        for (int i = 0; i < 4; ++i) {
            float v = er[lane + 32 * i];
            s = fmaf(v, v, s);
        }
        s = xla_warp_tree(s);
        if (lane == 0) e2_g[c][k] = s;
    }
}

// stage ROWS x 128 f32 source into two bf16 split tiles (hi, lo residual)
template<int ITERS>
__device__ __forceinline__ void stage_split(const float* __restrict__ src, int srcld,
                                            char* t1, char* t2, int t) {
    #pragma unroll
    for (int i = 0; i < ITERS; ++i) {
        int f4 = t + i * THREADS;
        int r = f4 >> 5, d4 = f4 & 31;
        float4 v = *(const float4*)(src + (size_t)r * srcld + 4 * d4);
        float h0 = __bfloat162float(__float2bfloat16_rn(v.x));
        float h1 = __bfloat162float(__float2bfloat16_rn(v.y));
        float h2 = __bfloat162float(__float2bfloat16_rn(v.z));
        float h3 = __bfloat162float(__float2bfloat16_rn(v.w));
        uint2 w1, w2;
        w1.x = bf2_pack(v.x, v.y);
        w1.y = bf2_pack(v.z, v.w);
        w2.x = bf2_pack(v.x - h0, v.y - h1);
        w2.y = bf2_pack(v.z - h2, v.w - h3);
        size_t off = (size_t)r * TROWB + 8 * d4;
        *(uint2*)(t1 + off) = w1;
        *(uint2*)(t2 + off) = w2;
    }
}

__global__ __launch_bounds__(THREADS, 2)
void pvq_kernel(const float* __restrict__ inp,
                const float* __restrict__ emb,
                float* __restrict__ out_q,
                float* __restrict__ out_idx,
                float* __restrict__ out_loss,
                int write_aux)
{
    extern __shared__ char sm[];
    float* e2s     = (float*)(sm + OFF_E2S);
    float* x2s     = (float*)(sm + OFF_X2S);
    float* lossacc = (float*)(sm + OFF_LOSS);
    int*   bestk   = (int*)(sm + OFF_BESTK);
    int*   idxacc  = (int*)(sm + OFF_IDXA);
    int*   flags   = (int*)(sm + OFF_FLAGS);
    float* hbs     = (float*)(sm + OFF_HBS);
    float* hbs2    = (float*)(sm + OFF_HBS2);
    int*   hbk     = (int*)(sm + OFF_HBK);
    int*   nflag   = (int*)(sm + OFF_NFLAG);

    const uint32_t sb = smem_u32(sm);
    const int t    = threadIdx.x;
    const int lane = t & 31;
    const int warp = t >> 5;               // 8 warps
    const int wm   = warp & 3;             // 16-row set
    const int wn   = warp >> 2;            // code half (64 codes)
    const int row0 = blockIdx.x * ROWS_PER_BLOCK;

    // A-side ldmatrix per-lane address (m16k16, row-major)
    const int rA = (lane & 7) + ((lane >> 3) & 1) * 8;
    const int cA = (lane >> 4);
    const uint32_t aOff = (uint32_t)(wm * 16 + rA) * TROWB + cA * 16;
    // B-side ldmatrix.x4 per-lane address (two n8 tiles x two k-halves)
    const int rB = (lane & 7) + ((lane >> 4) << 3);  // code within 16
    const int hB = (lane >> 3) & 1;                  // k half
    const uint32_t bOff = (uint32_t)(wn * 64 + rB) * TROWB + hB * 16;

    if (t < ROWS_PER_BLOCK) { lossacc[t] = 0.0f; idxacc[t] = 0; }

    int powc = KCODES * KCODES * KCODES;   // 128^3, /128 per group

    for (int c = 0; c < CGROUPS; ++c) {
        // ---- stage bf16 split tiles ----
        stage_split<(ROWS_PER_BLOCK * DSUB / 4) / THREADS>(     // 8 iters
            inp + (size_t)row0 * DFULL + c * DSUB, DFULL,
            sm + OFF_XB1, sm + OFF_XB2, t);
        stage_split<(KCODES * DSUB / 4) / THREADS>(             // 16 iters
            emb + (size_t)c * KCODES * DSUB, DSUB,
            sm + OFF_EB1, sm + OFF_EB2, t);
        if (t < KCODES) e2s[t] = e2_g[c][t];
        if (t == 0) *nflag = 0;
        __syncthreads();

        // ---- x2[r]: exact XLA warp pattern from GLOBAL (L2-hot) ----
        #pragma unroll
        for (int it = 0; it < ROWS_PER_BLOCK / 8; ++it) {       // 8 rows per warp
            int r = warp * 8 + it;
            const float* xr = inp + (size_t)(row0 + r) * DFULL + c * DSUB;
            float s = 0.0f;
            #pragma unroll
            for (int i = 0; i < 4; ++i) {
                float v = xr[lane + 32 * i];
                s = fmaf(v, v, s);
            }
            s = xla_warp_tree(s);
            if (lane == 0) x2s[r] = s;
        }

        // ---- HMMA GEMM: 16 rows x 64 codes per warp; 3 split passes ----
        float acc[8][4];
        #pragma unroll
        for (int nt = 0; nt < 8; ++nt)
            #pragma unroll
            for (int j = 0; j < 4; ++j) acc[nt][j] = 0.0f;

        const uint32_t a1A = sb + OFF_XB1 + aOff;
        const uint32_t a2A = sb + OFF_XB2 + aOff;
        const uint32_t b1A = sb + OFF_EB1 + bOff;
        const uint32_t b2A = sb + OFF_EB2 + bOff;

        #pragma unroll
        for (int kk = 0; kk < 8; ++kk) {
            uint32_t ra1[4], ra2[4];
            ldmx4(ra1, a1A + kk * 32);
            ldmx4(ra2, a2A + kk * 32);
            #pragma unroll
            for (int p = 0; p < 4; ++p) {                // 2 n8-tiles per ldmx4
                uint32_t rb1[4], rb2[4];
                uint32_t bo = kk * 32 + p * (16 * TROWB);
                ldmx4(rb1, b1A + bo);
                ldmx4(rb2, b2A + bo);
                mma_bf16(acc[2 * p],     ra1, rb1);      // x1*e1 (n tile 0)
                mma_bf16(acc[2 * p],     ra1, rb2 );     // x1*e2
                mma_bf16(acc[2 * p],     ra2, rb1);      // x2*e1
                mma_bf16(acc[2 * p + 1], ra1, rb1 + 2);  // n tile 1
                mma_bf16(acc[2 * p + 1], ra1, rb2 + 2);
                mma_bf16(acc[2 * p + 1], ra2, rb1 + 2);
            }
        }
        __syncthreads();   // x2s visible

        // ---- approx scores + per-half argmin (4 lanes per row) ----
        {
            int q = lane & 3;                 // 2-col group
            int g = lane >> 2;                // row-in-16 group 0..7
            #pragma unroll
            for (int half = 0; half < 2; ++half) {
                int row = wm * 16 + g + 8 * half;
                float x2v = x2s[row];
                float bs = __int_as_float(0x7f800000), bs2 = bs;
                int   bk = 0;
                #pragma unroll
                for (int nt = 0; nt < 8; ++nt) {
                    int k0 = wn * 64 + 8 * nt + 2 * q;
                    float s0 = (x2v + e2s[k0])     - 2.0f * acc[nt][2 * half + 0];
                    float s1 = (x2v + e2s[k0 + 1]) - 2.0f * acc[nt][2 * half + 1];
                    if (s0 < bs) { bs2 = bs; bs = s0; bk = k0; }
                    else if (s0 < bs2) { bs2 = s0; }
                    if (s1 < bs) { bs2 = bs; bs = s1; bk = k0 + 1; }
                    else if (s1 < bs2) { bs2 = s1; }
                }
                #pragma unroll
                for (int off = 1; off <= 2; off <<= 1) {
                    float os  = __shfl_xor_sync(0xffffffffu, bs, off);
                    int   ok  = __shfl_xor_sync(0xffffffffu, bk, off);
                    float os2 = __shfl_xor_sync(0xffffffffu, bs2, off);
                    if (os < bs || (os == bs && ok < bk)) {
                        bs2 = fminf(bs, os2);
                        bs = os; bk = ok;
                    } else {
                        bs2 = fminf(bs2, os);
                    }
                }
                if (q == 0) {
                    hbs[row * 2 + wn]  = bs;
                    hbs2[row * 2 + wn] = bs2;
                    hbk[row * 2 + wn]  = bk;
                }
            }
        }
        __syncthreads();

        // ---- combine halves, final argmin + flagging ----
        if (t < ROWS_PER_BLOCK) {
            float b0 = hbs[t * 2], b1 = hbs[t * 2 + 1];
            int   k0 = hbk[t * 2], k1 = hbk[t * 2 + 1];
            float s20 = hbs2[t * 2], s21 = hbs2[t * 2 + 1];
            float bs, bs2; int bk;
            if (b0 < b1 || (b0 == b1 && k0 < k1)) {
                bs = b0; bk = k0; bs2 = fminf(s20, b1);
            } else {
                bs = b1; bk = k1; bs2 = fminf(s21, b0);
            }
            bestk[t] = bk;
            if (bs2 - bs < TAU) {
                int pos = atomicAdd(nflag, 1);
                flags[pos] = t;
            }
        }
        __syncthreads();

        // ---- exact recheck for flagged rows (rare): bit-exact reference math ----
        {
            int nf = *nflag;
            for (int i = warp; i < nf; i += 8) {
                int row = flags[i];
                const float* xg = inp + (size_t)(row0 + row) * DFULL + c * DSUB;
                float x2v = x2s[row];
                float bs = __int_as_float(0x7f800000);
                int   bk = 0;
                #pragma unroll
                for (int kb = 0; kb < 4; ++kb) {
                    int k = kb * 32 + lane;
                    const float* eg = emb + ((size_t)c * KCODES + k) * DSUB;
                    float dt = 0.0f;
                    for (int dd = 0; dd < DSUB; ++dd)
                        dt = fmaf(xg[dd], eg[dd], dt);       // sequential, ascending
                    float sc = (x2v + e2s[k]) - 2.0f * dt;   // reference rounding
                    if (sc < bs) { bs = sc; bk = k; }        // lane ks ascending
                }
                #pragma unroll
                for (int off = 16; off >= 1; off >>= 1) {
                    float os = __shfl_xor_sync(0xffffffffu, bs, off);
                    int   ok = __shfl_xor_sync(0xffffffffu, bk, off);
                    if (os < bs || (os == bs && ok < bk)) { bs = os; bk = ok; }
                }
                if (lane == 0) bestk[row] = bk;
            }
        }
        __syncthreads();

        // ---- index accumulation + epilogue (quantized_sg, loss) from GLOBAL ----
        if (t < ROWS_PER_BLOCK) idxacc[t] += bestk[t] * powc;
        #pragma unroll
        for (int rr = 0; rr < ROWS_PER_BLOCK / 8; ++rr) {   // 8 rows per warp
            int r = warp * 8 + rr;
            int k = bestk[r];
            const float* eg = emb + ((size_t)c * KCODES + k) * DSUB;
            const float* xg = inp + (size_t)(row0 + r) * DFULL + c * DSUB;
            float* qrow = out_q + (size_t)(row0 + r) * DFULL + c * DSUB;

            float part = 0.0f;
            #pragma unroll
            for (int m = 0; m < 4; ++m) {
                int dd = lane + 32 * m;
                float ev = eg[dd];
                float xv = xg[dd];
                float dlt = ev - xv;
                part = fmaf(dlt, dlt, part);
                qrow[dd] = xv + dlt;                    // x + (q - x), matches ref
            }
            #pragma unroll
            for (int off = 16; off >= 1; off >>= 1)
                part += __shfl_xor_sync(0xffffffffu, part, off);
            if (lane == 0) lossacc[r] += part;
        }
        powc >>= 7;  // /128
        __syncthreads();
    }

    if (write_aux && t < ROWS_PER_BLOCK) {
        int n = row0 + t;
        out_idx[n] = (float)idxacc[t];
        float d2 = lossacc[t];
        out_loss[n] = d2 + 0.25f * d2;   // q_latent + 0.25*e_latent
    }
}

extern "C" void kernel_launch(void* const* d_in, const int* in_sizes, int n_in,
                              void* d_out, int out_size) {
    const float* inp = (const float*)d_in[0];   // inputs (64,2048,512) f32
    const float* emb = (const float*)d_in[1];   // embeddings (4,128,128) f32
    float* out = (float*)d_out;

    const long long QN = (long long)NROWS * DFULL;
    int write_aux = ((long long)out_size >= QN + 2LL * NROWS) ? 1 : 0;
    float* out_q    = out;
    float* out_idx  = out + QN;
    float* out_loss = out + QN + NROWS;

    pre_kernel<<<16, 256>>>(emb);

    cudaFuncSetAttribute(pvq_kernel,
                         cudaFuncAttributeMaxDynamicSharedMemorySize, SMEM_BYTES);
    pvq_kernel<<<NROWS / ROWS_PER_BLOCK, THREADS, SMEM_BYTES>>>(
        inp, emb, out_q, out_idx, out_loss, write_aux);
}

// round 15
// speedup vs baseline: 3.0472x; 1.1031x over previous
#include <cuda_runtime.h>
#include <cuda_bf16.h>
#include <cstdint>
#include <cstddef>

// Problem constants (fixed shapes)
#define NROWS   131072          // B*T = 64*2048
#define CGROUPS 4
#define DSUB    128             // d = D/C
#define KCODES  128
#define DFULL   512

#define ROWS_PER_BLOCK 64
#define THREADS 256             // 8 warps = 4 row-sets (16 rows) x 2 code-halves (64)
#define TAU     0.05f           // near-tie threshold for exact recheck

// bf16 tile rows: 136 bf16 stride (272 B) -> conflict-free ldmatrix
#define TROW    136
#define TROWB   (TROW * 2)                  // 272 bytes
#define XTILE_B (ROWS_PER_BLOCK * TROWB)    // 17408
#define ETILE_B (KCODES * TROWB)            // 34816

// smem layout (BYTE offsets)
#define OFF_XB1   0
#define OFF_XB2   (XTILE_B)                         // 17408
#define OFF_EB1   (2 * XTILE_B)                     // 34816  (EB1+EB2 contiguous)
#define OFF_EB2   (2 * XTILE_B + ETILE_B)           // 69632
#define OFF_AUX   (2 * XTILE_B + 2 * ETILE_B)       // 104448
#define OFF_E2S   (OFF_AUX)                         // f32[128]
#define OFF_X2S   (OFF_AUX + 512)                   // f32[64]
#define OFF_LOSS  (OFF_AUX + 768)                   // f32[64]
#define OFF_BESTK (OFF_AUX + 1024)                  // int[64]
#define OFF_IDXA  (OFF_AUX + 1280)                  // int[64]
#define OFF_FLAGS (OFF_AUX + 1536)                  // int[64]
#define OFF_HBS   (OFF_AUX + 1792)                  // f32[64][2]
#define OFF_HBS2  (OFF_AUX + 2304)                  // f32[64][2]
#define OFF_HBK   (OFF_AUX + 2816)                  // int[64][2]
#define OFF_NFLAG (OFF_AUX + 3328)                  // int
#define SMEM_BYTES (OFF_AUX + 3344)                 // 107792 (2 CTAs/SM)

// global scratch (written by pre_kernel):
//  - e2_g: exact XLA-order squared norms
//  - etimg_g: per-group byte image of the two E smem tiles (hi || lo)
__device__ float e2_g[CGROUPS][KCODES];
__device__ __align__(16) uint4 etimg_g[CGROUPS][2 * ETILE_B / 16];

// ---------------- helpers ----------------
__device__ __forceinline__ uint32_t smem_u32(const void* p) {
    uint32_t a;
    asm("{ .reg .u64 t; cvta.to.shared.u64 t, %1; cvt.u32.u64 %0, t; }"
        : "=r"(a) : "l"(p));
    return a;
}
__device__ __forceinline__ void ldmx4(uint32_t* r, uint32_t addr) {
    asm volatile("ldmatrix.sync.aligned.m8n8.x4.shared.b16 {%0,%1,%2,%3}, [%4];"
                 : "=r"(r[0]), "=r"(r[1]), "=r"(r[2]), "=r"(r[3]) : "r"(addr));
}
__device__ __forceinline__ void mma_bf16(float* c, const uint32_t* a, const uint32_t* b) {
    asm volatile(
        "mma.sync.aligned.m16n8k16.row.col.f32.bf16.bf16.f32 "
        "{%0,%1,%2,%3}, {%4,%5,%6,%7}, {%8,%9}, {%0,%1,%2,%3};"
        : "+f"(c[0]), "+f"(c[1]), "+f"(c[2]), "+f"(c[3])
        : "r"(a[0]), "r"(a[1]), "r"(a[2]), "r"(a[3]), "r"(b[0]), "r"(b[1]));
}
// XLA-style warp row-reduction: strided partials in s, shfl_down tree, sum in lane 0.
__device__ __forceinline__ float xla_warp_tree(float s) {
    s += __shfl_down_sync(0xffffffffu, s, 16);
    s += __shfl_down_sync(0xffffffffu, s, 8);
    s += __shfl_down_sync(0xffffffffu, s, 4);
    s += __shfl_down_sync(0xffffffffu, s, 2);
    s += __shfl_down_sync(0xffffffffu, s, 1);
    return s;
}
__device__ __forceinline__ uint32_t bf2_pack(float a, float b) {
    __nv_bfloat162 p = __halves2bfloat162(__float2bfloat16_rn(a), __float2bfloat16_rn(b));
    return *(uint32_t*)&p;
}

// ---- pre-kernel: split-E tile images + e2_g ----
__global__ __launch_bounds__(256)
void pre_kernel(const float* __restrict__ emb) {
    int b = blockIdx.x;
    int t = threadIdx.x;
    if (b < 64) {
        // build E tile images: one thread per (c, k, d4)
        int idx = b * 256 + t;                 // 0..16383
        int c  = idx >> 12;
        int rem = idx & 4095;
        int k  = rem >> 5, d4 = rem & 31;
        float4 v = *(const float4*)(emb + ((size_t)c * KCODES + k) * DSUB + 4 * d4);
        float h0 = __bfloat162float(__float2bfloat16_rn(v.x));
        float h1 = __bfloat162float(__float2bfloat16_rn(v.y));
        float h2 = __bfloat162float(__float2bfloat16_rn(v.z));
        float h3 = __bfloat162float(__float2bfloat16_rn(v.w));
        uint2 w1, w2;
        w1.x = bf2_pack(v.x, v.y);
        w1.y = bf2_pack(v.z, v.w);
        w2.x = bf2_pack(v.x - h0, v.y - h1);
        w2.y = bf2_pack(v.z - h2, v.w - h3);
        char* img = (char*)etimg_g[c];
        size_t o = (size_t)k * TROWB + 8 * d4;
        *(uint2*)(img + o)           = w1;     // hi tile
        *(uint2*)(img + ETILE_B + o) = w2;     // lo tile
    } else {
        // e2: exact XLA reduce order
        int lane = t & 31;
        int w = (b - 64) * 8 + (t >> 5);       // 0..127
        #pragma unroll
        for (int kk = 0; kk < 4; ++kk) {
            int kidx = w * 4 + kk;             // 0..511
            int c = kidx >> 7, k = kidx & 127;
            const float* er = emb + ((size_t)c * KCODES + k) * DSUB;
            float s = 0.0f;
            #pragma unroll
            for (int i = 0; i < 4; ++i) {
                float v = er[lane + 32 * i];
                s = fmaf(v, v, s);
            }
            s = xla_warp_tree(s);
            if (lane == 0) e2_g[c][k] = s;
        }
    }
}

__global__ __launch_bounds__(THREADS, 2)
void pvq_kernel(const float* __restrict__ inp,
                const float* __restrict__ emb,
                float* __restrict__ out_q,
                float* __restrict__ out_idx,
                float* __restrict__ out_loss,
                int write_aux)
{
    extern __shared__ char sm[];
    float* e2s     = (float*)(sm + OFF_E2S);
    float* x2s     = (float*)(sm + OFF_X2S);
    float* lossacc = (float*)(sm + OFF_LOSS);
    int*   bestk   = (int*)(sm + OFF_BESTK);
    int*   idxacc  = (int*)(sm + OFF_IDXA);
    int*   flags   = (int*)(sm + OFF_FLAGS);
    float* hbs     = (float*)(sm + OFF_HBS);
    float* hbs2    = (float*)(sm + OFF_HBS2);
    int*   hbk     = (int*)(sm + OFF_HBK);
    int*   nflag   = (int*)(sm + OFF_NFLAG);

    const uint32_t sb = smem_u32(sm);
    const int t    = threadIdx.x;
    const int lane = t & 31;
    const int warp = t >> 5;               // 8 warps
    const int wm   = warp & 3;             // 16-row set
    const int wn   = warp >> 2;            // code half (64 codes)
    const int row0 = blockIdx.x * ROWS_PER_BLOCK;

    // A-side ldmatrix per-lane address (m16k16, row-major)
    const int rA = (lane & 7) + ((lane >> 3) & 1) * 8;
    const int cA = (lane >> 4);
    const uint32_t aOff = (uint32_t)(wm * 16 + rA) * TROWB + cA * 16;
    // B-side ldmatrix.x4 per-lane address (two n8 tiles x two k-halves)
    const int rB = (lane & 7) + ((lane >> 4) << 3);  // code within 16
    const int hB = (lane >> 3) & 1;                  // k half
    const uint32_t bOff = (uint32_t)(wn * 64 + rB) * TROWB + hB * 16;

    if (t < ROWS_PER_BLOCK) { lossacc[t] = 0.0f; idxacc[t] = 0; }

    int powc = KCODES * KCODES * KCODES;   // 128^3, /128 per group

    for (int c = 0; c < CGROUPS; ++c) {
        // ---- E tiles: bulk cp.async copy of precomputed split image ----
        {
            const char* src = (const char*)etimg_g[c];
            #pragma unroll
            for (int i = 0; i < (2 * ETILE_B) / (THREADS * 16); ++i) {  // 17 iters
                uint32_t dst = sb + OFF_EB1 + (uint32_t)(t + i * THREADS) * 16;
                const char* s = src + (size_t)(t + i * THREADS) * 16;
                asm volatile("cp.async.cg.shared.global [%0], [%1], 16;"
                             :: "r"(dst), "l"(s));
            }
            asm volatile("cp.async.commit_group;");
        }
        // ---- stage x split tiles (convert in-flight while E copies) ----
        {
            #pragma unroll
            for (int i = 0; i < (ROWS_PER_BLOCK * DSUB / 4) / THREADS; ++i) {  // 8
                int f4 = t + i * THREADS;
                int r = f4 >> 5, d4 = f4 & 31;
                float4 v = *(const float4*)(inp + (size_t)(row0 + r) * DFULL
                                            + c * DSUB + 4 * d4);
                float h0 = __bfloat162float(__float2bfloat16_rn(v.x));
                float h1 = __bfloat162float(__float2bfloat16_rn(v.y));
                float h2 = __bfloat162float(__float2bfloat16_rn(v.z));
                float h3 = __bfloat162float(__float2bfloat16_rn(v.w));
                uint2 w1, w2;
                w1.x = bf2_pack(v.x, v.y);
                w1.y = bf2_pack(v.z, v.w);
                w2.x = bf2_pack(v.x - h0, v.y - h1);
                w2.y = bf2_pack(v.z - h2, v.w - h3);
                size_t off = (size_t)r * TROWB + 8 * d4;
                *(uint2*)(sm + OFF_XB1 + off) = w1;
                *(uint2*)(sm + OFF_XB2 + off) = w2;
            }
        }
        if (t < KCODES) e2s[t] = e2_g[c][t];
        if (t == 0) *nflag = 0;

        // ---- x2[r]: exact XLA warp pattern from GLOBAL (L2-hot) ----
        #pragma unroll
        for (int it = 0; it < ROWS_PER_BLOCK / 8; ++it) {       // 8 rows per warp
            int r = warp * 8 + it;
            const float* xr = inp + (size_t)(row0 + r) * DFULL + c * DSUB;
            float s = 0.0f;
            #pragma unroll
            for (int i = 0; i < 4; ++i) {
                float v = xr[lane + 32 * i];
                s = fmaf(v, v, s);
            }
            s = xla_warp_tree(s);
            if (lane == 0) x2s[r] = s;
        }

        asm volatile("cp.async.wait_group 0;" ::: "memory");
        __syncthreads();   // tiles + e2s + x2s all visible

        // ---- HMMA GEMM: 16 rows x 64 codes per warp; 3 split passes ----
        float acc[8][4];
        #pragma unroll
        for (int nt = 0; nt < 8; ++nt)
            #pragma unroll
            for (int j = 0; j < 4; ++j) acc[nt][j] = 0.0f;

        const uint32_t a1A = sb + OFF_XB1 + aOff;
        const uint32_t a2A = sb + OFF_XB2 + aOff;
        const uint32_t b1A = sb + OFF_EB1 + bOff;
        const uint32_t b2A = sb + OFF_EB2 + bOff;

        #pragma unroll
        for (int kk = 0; kk < 8; ++kk) {
            uint32_t ra1[4], ra2[4];
            ldmx4(ra1, a1A + kk * 32);
            ldmx4(ra2, a2A + kk * 32);
            #pragma unroll
            for (int p = 0; p < 4; ++p) {                // 2 n8-tiles per ldmx4
                uint32_t rb1[4], rb2[4];
                uint32_t bo = kk * 32 + p * (16 * TROWB);
                ldmx4(rb1, b1A + bo);
                ldmx4(rb2, b2A + bo);
                mma_bf16(acc[2 * p],     ra1, rb1);      // x1*e1 (n tile 0)
                mma_bf16(acc[2 * p],     ra1, rb2);      // x1*e2
                mma_bf16(acc[2 * p],     ra2, rb1);      // x2*e1
                mma_bf16(acc[2 * p + 1], ra1, rb1 + 2);  // n tile 1
                mma_bf16(acc[2 * p + 1], ra1, rb2 + 2);
                mma_bf16(acc[2 * p + 1], ra2, rb1 + 2);
            }
        }
        __syncthreads();

        // ---- approx scores + per-half argmin (4 lanes per row) ----
        {
            int q = lane & 3;                 // 2-col group
            int g = lane >> 2;                // row-in-16 group 0..7
            #pragma unroll
            for (int half = 0; half < 2; ++half) {
                int row = wm * 16 + g + 8 * half;
                float x2v = x2s[row];
                float bs = __int_as_float(0x7f800000), bs2 = bs;
                int   bk = 0;
                #pragma unroll
                for (int nt = 0; nt < 8; ++nt) {
                    int k0 = wn * 64 + 8 * nt + 2 * q;
                    float s0 = (x2v + e2s[k0])     - 2.0f * acc[nt][2 * half + 0];
                    float s1 = (x2v + e2s[k0 + 1]) - 2.0f * acc[nt][2 * half + 1];
                    if (s0 < bs) { bs2 = bs; bs = s0; bk = k0; }
                    else if (s0 < bs2) { bs2 = s0; }
                    if (s1 < bs) { bs2 = bs; bs = s1; bk = k0 + 1; }
                    else if (s1 < bs2) { bs2 = s1; }
                }
                #pragma unroll
                for (int off = 1; off <= 2; off <<= 1) {
                    float os  = __shfl_xor_sync(0xffffffffu, bs, off);
                    int   ok  = __shfl_xor_sync(0xffffffffu, bk, off);
                    float os2 = __shfl_xor_sync(0xffffffffu, bs2, off);
                    if (os < bs || (os == bs && ok < bk)) {
                        bs2 = fminf(bs, os2);
                        bs = os; bk = ok;
                    } else {
                        bs2 = fminf(bs2, os);
                    }
                }
                if (q == 0) {
                    hbs[row * 2 + wn]  = bs;
                    hbs2[row * 2 + wn] = bs2;
                    hbk[row * 2 + wn]  = bk;
                }
            }
        }
        __syncthreads();

        // ---- combine halves, final argmin + flagging ----
        if (t < ROWS_PER_BLOCK) {
            float b0 = hbs[t * 2], b1 = hbs[t * 2 + 1];
            int   k0 = hbk[t * 2], k1 = hbk[t * 2 + 1];
            float s20 = hbs2[t * 2], s21 = hbs2[t * 2 + 1];
            float bs, bs2; int bk;
            if (b0 < b1 || (b0 == b1 && k0 < k1)) {
                bs = b0; bk = k0; bs2 = fminf(s20, b1);
            } else {
                bs = b1; bk = k1; bs2 = fminf(s21, b0);
            }
            bestk[t] = bk;
            if (bs2 - bs < TAU) {
                int pos = atomicAdd(nflag, 1);
                flags[pos] = t;
            }
        }
        __syncthreads();

        // ---- exact recheck for flagged rows (rare): bit-exact reference math ----
        {
            int nf = *nflag;
            for (int i = warp; i < nf; i += 8) {
                int row = flags[i];
                const float* xg = inp + (size_t)(row0 + row) * DFULL + c * DSUB;
                float x2v = x2s[row];
                float bs = __int_as_float(0x7f800000);
                int   bk = 0;
                #pragma unroll
                for (int kb = 0; kb < 4; ++kb) {
                    int k = kb * 32 + lane;
                    const float* eg = emb + ((size_t)c * KCODES + k) * DSUB;
                    float dt = 0.0f;
                    for (int dd = 0; dd < DSUB; ++dd)
                        dt = fmaf(xg[dd], eg[dd], dt);       // sequential, ascending
                    float sc = (x2v + e2s[k]) - 2.0f * dt;   // reference rounding
                    if (sc < bs) { bs = sc; bk = k; }        // lane ks ascending
                }
                #pragma unroll
                for (int off = 16; off >= 1; off >>= 1) {
                    float os = __shfl_xor_sync(0xffffffffu, bs, off);
                    int   ok = __shfl_xor_sync(0xffffffffu, bk, off);
                    if (os < bs || (os == bs && ok < bk)) { bs = os; bk = ok; }
                }
                if (lane == 0) bestk[row] = bk;
            }
        }
        __syncthreads();

        // ---- index accumulation + epilogue (quantized_sg, loss) from GLOBAL ----
        if (t < ROWS_PER_BLOCK) idxacc[t] += bestk[t] * powc;
        #pragma unroll
        for (int rr = 0; rr < ROWS_PER_BLOCK / 8; ++rr) {   // 8 rows per warp
            int r = warp * 8 + rr;
            int k = bestk[r];
            const float* eg = emb + ((size_t)c * KCODES + k) * DSUB;
            const float* xg = inp + (size_t)(row0 + r) * DFULL + c * DSUB;
            float* qrow = out_q + (size_t)(row0 + r) * DFULL + c * DSUB;

            float part = 0.0f;
            #pragma unroll
            for (int m = 0; m < 4; ++m) {
                int dd = lane + 32 * m;
                float ev = eg[dd];
                float xv = xg[dd];
                float dlt = ev - xv;
                part = fmaf(dlt, dlt, part);
                qrow[dd] = xv + dlt;                    // x + (q - x), matches ref
            }
            #pragma unroll
            for (int off = 16; off >= 1; off >>= 1)
                part += __shfl_xor_sync(0xffffffffu, part, off);
            if (lane == 0) lossacc[r] += part;
        }
        powc >>= 7;  // /128
        __syncthreads();
    }

    if (write_aux && t < ROWS_PER_BLOCK) {
        int n = row0 + t;
        out_idx[n] = (float)idxacc[t];
        float d2 = lossacc[t];
        out_loss[n] = d2 + 0.25f * d2;   // q_latent + 0.25*e_latent
    }
}

extern "C" void kernel_launch(void* const* d_in, const int* in_sizes, int n_in,
                              void* d_out, int out_size) {
    const float* inp = (const float*)d_in[0];   // inputs (64,2048,512) f32
    const float* emb = (const float*)d_in[1];   // embeddings (4,128,128) f32
    float* out = (float*)d_out;

    const long long QN = (long long)NROWS * DFULL;
    int write_aux = ((long long)out_size >= QN + 2LL * NROWS) ? 1 : 0;
    float* out_q    = out;
    float* out_idx  = out + QN;
    float* out_loss = out + QN + NROWS;

    pre_kernel<<<80, 256>>>(emb);

    cudaFuncSetAttribute(pvq_kernel,
                         cudaFuncAttributeMaxDynamicSharedMemorySize, SMEM_BYTES);
    pvq_kernel<<<NROWS / ROWS_PER_BLOCK, THREADS, SMEM_BYTES>>>(
        inp, emb, out_q, out_idx, out_loss, write_aux);
}

// round 16
// speedup vs baseline: 3.3355x; 1.0946x over previous
#include <cuda_runtime.h>
#include <cuda_bf16.h>
#include <cstdint>
#include <cstddef>

// Problem constants (fixed shapes)
#define NROWS   131072          // B*T = 64*2048
#define CGROUPS 4
#define DSUB    128             // d = D/C
#define KCODES  128
#define DFULL   512

#define ROWS_PER_BLOCK 64
#define THREADS 256             // 8 warps = 2 row-sets (32 rows) x 4 code-quarters (32)
#define TAU     0.05f           // near-tie threshold for exact recheck

// bf16 tile rows: 136 bf16 stride (272 B) -> conflict-free ldmatrix
#define TROW    136
#define TROWB   (TROW * 2)                  // 272 bytes
#define XTILE_B (ROWS_PER_BLOCK * TROWB)    // 17408
#define ETILE_B (KCODES * TROWB)            // 34816

// smem layout (BYTE offsets)
#define OFF_XB1   0
#define OFF_XB2   (XTILE_B)                         // 17408
#define OFF_EB1   (2 * XTILE_B)                     // 34816  (EB1+EB2 contiguous)
#define OFF_EB2   (2 * XTILE_B + ETILE_B)           // 69632
#define OFF_AUX   (2 * XTILE_B + 2 * ETILE_B)       // 104448
#define OFF_E2S   (OFF_AUX)                         // f32[128]
#define OFF_LOSS  (OFF_AUX + 512)                   // f32[64]
#define OFF_BESTK (OFF_AUX + 768)                   // int[64]
#define OFF_IDXA  (OFF_AUX + 1024)                  // int[64]
#define OFF_FLAGS (OFF_AUX + 1280)                  // int[64]
#define OFF_HBS   (OFF_AUX + 1536)                  // f32[64][4]
#define OFF_HBS2  (OFF_AUX + 2560)                  // f32[64][4]
#define OFF_HBK   (OFF_AUX + 3584)                  // int[64][4]
#define OFF_NFLAG (OFF_AUX + 4608)                  // int
#define SMEM_BYTES (OFF_AUX + 4624)                 // 109072 (2 CTAs/SM)

// global scratch (written by pre_kernel):
//  - e2_g: exact XLA-order squared norms
//  - etimg_g: per-group byte image of the two E smem tiles (hi || lo)
__device__ float e2_g[CGROUPS][KCODES];
__device__ __align__(16) uint4 etimg_g[CGROUPS][2 * ETILE_B / 16];

// ---------------- helpers ----------------
__device__ __forceinline__ uint32_t smem_u32(const void* p) {
    uint32_t a;
    asm("{ .reg .u64 t; cvta.to.shared.u64 t, %1; cvt.u32.u64 %0, t; }"
        : "=r"(a) : "l"(p));
    return a;
}
__device__ __forceinline__ void ldmx4(uint32_t* r, uint32_t addr) {
    asm volatile("ldmatrix.sync.aligned.m8n8.x4.shared.b16 {%0,%1,%2,%3}, [%4];"
                 : "=r"(r[0]), "=r"(r[1]), "=r"(r[2]), "=r"(r[3]) : "r"(addr));
}
__device__ __forceinline__ void mma_bf16(float* c, const uint32_t* a, const uint32_t* b) {
    asm volatile(
        "mma.sync.aligned.m16n8k16.row.col.f32.bf16.bf16.f32 "
        "{%0,%1,%2,%3}, {%4,%5,%6,%7}, {%8,%9}, {%0,%1,%2,%3};"
        : "+f"(c[0]), "+f"(c[1]), "+f"(c[2]), "+f"(c[3])
        : "r"(a[0]), "r"(a[1]), "r"(a[2]), "r"(a[3]), "r"(b[0]), "r"(b[1]));
}
// XLA-style warp row-reduction: strided partials in s, shfl_down tree, sum in lane 0.
__device__ __forceinline__ float xla_warp_tree(float s) {
    s += __shfl_down_sync(0xffffffffu, s, 16);
    s += __shfl_down_sync(0xffffffffu, s, 8);
    s += __shfl_down_sync(0xffffffffu, s, 4);
    s += __shfl_down_sync(0xffffffffu, s, 2);
    s += __shfl_down_sync(0xffffffffu, s, 1);
    return s;
}
__device__ __forceinline__ uint32_t bf2_pack(float a, float b) {
    __nv_bfloat162 p = __halves2bfloat162(__float2bfloat16_rn(a), __float2bfloat16_rn(b));
    return *(uint32_t*)&p;
}

// ---- pre-kernel: split-E tile images + e2_g ----
__global__ __launch_bounds__(256)
void pre_kernel(const float* __restrict__ emb) {
    int b = blockIdx.x;
    int t = threadIdx.x;
    if (b < 64) {
        // build E tile images: one thread per (c, k, d4)
        int idx = b * 256 + t;                 // 0..16383
        int c  = idx >> 12;
        int rem = idx & 4095;
        int k  = rem >> 5, d4 = rem & 31;
        float4 v = *(const float4*)(emb + ((size_t)c * KCODES + k) * DSUB + 4 * d4);
        float h0 = __bfloat162float(__float2bfloat16_rn(v.x));
        float h1 = __bfloat162float(__float2bfloat16_rn(v.y));
        float h2 = __bfloat162float(__float2bfloat16_rn(v.z));
        float h3 = __bfloat162float(__float2bfloat16_rn(v.w));
        uint2 w1, w2;
        w1.x = bf2_pack(v.x, v.y);
        w1.y = bf2_pack(v.z, v.w);
        w2.x = bf2_pack(v.x - h0, v.y - h1);
        w2.y = bf2_pack(v.z - h2, v.w - h3);
        char* img = (char*)etimg_g[c];
        size_t o = (size_t)k * TROWB + 8 * d4;
        *(uint2*)(img + o)           = w1;     // hi tile
        *(uint2*)(img + ETILE_B + o) = w2;     // lo tile
    } else {
        // e2: exact XLA reduce order
        int lane = t & 31;
        int w = (b - 64) * 8 + (t >> 5);       // 0..127
        #pragma unroll
        for (int kk = 0; kk < 4; ++kk) {
            int kidx = w * 4 + kk;             // 0..511
            int c = kidx >> 7, k = kidx & 127;
            const float* er = emb + ((size_t)c * KCODES + k) * DSUB;
            float s = 0.0f;
            #pragma unroll
            for (int i = 0; i < 4; ++i) {
                float v = er[lane + 32 * i];
                s = fmaf(v, v, s);
            }
            s = xla_warp_tree(s);
            if (lane == 0) e2_g[c][k] = s;
        }
    }
}

__global__ __launch_bounds__(THREADS, 2)
void pvq_kernel(const float* __restrict__ inp,
                const float* __restrict__ emb,
                float* __restrict__ out_q,
                float* __restrict__ out_idx,
                float* __restrict__ out_loss,
                int write_aux)
{
    extern __shared__ char sm[];
    float* e2s     = (float*)(sm + OFF_E2S);
    float* lossacc = (float*)(sm + OFF_LOSS);
    int*   bestk   = (int*)(sm + OFF_BESTK);
    int*   idxacc  = (int*)(sm + OFF_IDXA);
    int*   flags   = (int*)(sm + OFF_FLAGS);
    float* hbs     = (float*)(sm + OFF_HBS);
    float* hbs2    = (float*)(sm + OFF_HBS2);
    int*   hbk     = (int*)(sm + OFF_HBK);
    int*   nflag   = (int*)(sm + OFF_NFLAG);

    const uint32_t sb = smem_u32(sm);
    const int t    = threadIdx.x;
    const int lane = t & 31;
    const int warp = t >> 5;               // 8 warps
    const int wm2  = warp & 1;             // 32-row set
    const int wq   = warp >> 1;            // code quarter (32 codes)
    const int row0 = blockIdx.x * ROWS_PER_BLOCK;

    // A-side ldmatrix per-lane address (m16k16, row-major), per m16 tile
    const int rA = (lane & 7) + ((lane >> 3) & 1) * 8;
    const int cA = (lane >> 4);
    const uint32_t aOff = (uint32_t)(wm2 * 32 + rA) * TROWB + cA * 16;
    // B-side ldmatrix.x4 per-lane address (two n8 tiles x two k-halves)
    const int rB = (lane & 7) + ((lane >> 4) << 3);  // code within 16
    const int hB = (lane >> 3) & 1;                  // k half
    const uint32_t bOff = (uint32_t)(wq * 32 + rB) * TROWB + hB * 16;

    if (t < ROWS_PER_BLOCK) { lossacc[t] = 0.0f; idxacc[t] = 0; }

    int powc = KCODES * KCODES * KCODES;   // 128^3, /128 per group

    for (int c = 0; c < CGROUPS; ++c) {
        // ---- E tiles: bulk cp.async copy of precomputed split image ----
        {
            const char* src = (const char*)etimg_g[c];
            #pragma unroll
            for (int i = 0; i < (2 * ETILE_B) / (THREADS * 16); ++i) {  // 17 iters
                uint32_t dst = sb + OFF_EB1 + (uint32_t)(t + i * THREADS) * 16;
                const char* s = src + (size_t)(t + i * THREADS) * 16;
                asm volatile("cp.async.cg.shared.global [%0], [%1], 16;"
                             :: "r"(dst), "l"(s));
            }
            asm volatile("cp.async.commit_group;");
        }
        // ---- stage x split tiles (convert in-flight while E copies) ----
        {
            #pragma unroll
            for (int i = 0; i < (ROWS_PER_BLOCK * DSUB / 4) / THREADS; ++i) {  // 8
                int f4 = t + i * THREADS;
                int r = f4 >> 5, d4 = f4 & 31;
                float4 v = *(const float4*)(inp + (size_t)(row0 + r) * DFULL
                                            + c * DSUB + 4 * d4);
                float h0 = __bfloat162float(__float2bfloat16_rn(v.x));
                float h1 = __bfloat162float(__float2bfloat16_rn(v.y));
                float h2 = __bfloat162float(__float2bfloat16_rn(v.z));
                float h3 = __bfloat162float(__float2bfloat16_rn(v.w));
                uint2 w1, w2;
                w1.x = bf2_pack(v.x, v.y);
                w1.y = bf2_pack(v.z, v.w);
                w2.x = bf2_pack(v.x - h0, v.y - h1);
                w2.y = bf2_pack(v.z - h2, v.w - h3);
                size_t off = (size_t)r * TROWB + 8 * d4;
                *(uint2*)(sm + OFF_XB1 + off) = w1;
                *(uint2*)(sm + OFF_XB2 + off) = w2;
            }
        }
        if (t < KCODES) e2s[t] = e2_g[c][t];
        if (t == 0) *nflag = 0;

        asm volatile("cp.async.wait_group 0;" ::: "memory");
        __syncthreads();   // tiles + e2s visible

        // ---- HMMA GEMM: 32 rows x 32 codes per warp; 3 split passes ----
        float acc[2][4][4];
        #pragma unroll
        for (int mt = 0; mt < 2; ++mt)
            #pragma unroll
            for (int nt = 0; nt < 4; ++nt)
                #pragma unroll
                for (int j = 0; j < 4; ++j) acc[mt][nt][j] = 0.0f;

        const uint32_t a1A = sb + OFF_XB1 + aOff;
        const uint32_t a2A = sb + OFF_XB2 + aOff;
        const uint32_t b1A = sb + OFF_EB1 + bOff;
        const uint32_t b2A = sb + OFF_EB2 + bOff;

        #pragma unroll
        for (int kk = 0; kk < 8; ++kk) {
            uint32_t ra1[2][4], ra2[2][4];
            #pragma unroll
            for (int mt = 0; mt < 2; ++mt) {
                ldmx4(ra1[mt], a1A + mt * (16 * TROWB) + kk * 32);
                ldmx4(ra2[mt], a2A + mt * (16 * TROWB) + kk * 32);
            }
            #pragma unroll
            for (int p = 0; p < 2; ++p) {
                uint32_t rb1[4], rb2[4];
                ldmx4(rb1, b1A + p * (16 * TROWB) + kk * 32);
                ldmx4(rb2, b2A + p * (16 * TROWB) + kk * 32);
                #pragma unroll
                for (int mt = 0; mt < 2; ++mt) {
                    mma_bf16(acc[mt][2 * p],     ra1[mt], rb1);      // x1*e1
                    mma_bf16(acc[mt][2 * p],     ra1[mt], rb2);      // x1*e2
                    mma_bf16(acc[mt][2 * p],     ra2[mt], rb1);      // x2*e1
                    mma_bf16(acc[mt][2 * p + 1], ra1[mt], rb1 + 2);  // n tile 1
                    mma_bf16(acc[mt][2 * p + 1], ra1[mt], rb2 + 2);
                    mma_bf16(acc[mt][2 * p + 1], ra2[mt], rb1 + 2);
                }
            }
        }
        __syncthreads();

        // ---- approx scores + per-quarter argmin (x2 dropped: row-constant) ----
        {
            int q = lane & 3;                 // 2-col group
            int g = lane >> 2;                // row-in-16 group 0..7
            #pragma unroll
            for (int mt = 0; mt < 2; ++mt) {
                #pragma unroll
                for (int half = 0; half < 2; ++half) {
                    int row = wm2 * 32 + mt * 16 + g + 8 * half;
                    float bs = __int_as_float(0x7f800000), bs2 = bs;
                    int   bk = 0;
                    #pragma unroll
                    for (int nt = 0; nt < 4; ++nt) {
                        int k0 = wq * 32 + 8 * nt + 2 * q;
                        float s0 = e2s[k0]     - 2.0f * acc[mt][nt][2 * half + 0];
                        float s1 = e2s[k0 + 1] - 2.0f * acc[mt][nt][2 * half + 1];
                        if (s0 < bs) { bs2 = bs; bs = s0; bk = k0; }
                        else if (s0 < bs2) { bs2 = s0; }
                        if (s1 < bs) { bs2 = bs; bs = s1; bk = k0 + 1; }
                        else if (s1 < bs2) { bs2 = s1; }
                    }
                    #pragma unroll
                    for (int off = 1; off <= 2; off <<= 1) {
                        float os  = __shfl_xor_sync(0xffffffffu, bs, off);
                        int   ok  = __shfl_xor_sync(0xffffffffu, bk, off);
                        float os2 = __shfl_xor_sync(0xffffffffu, bs2, off);
                        if (os < bs || (os == bs && ok < bk)) {
                            bs2 = fminf(bs, os2);
                            bs = os; bk = ok;
                        } else {
                            bs2 = fminf(bs2, os);
                        }
                    }
                    if (q == 0) {
                        hbs[row * 4 + wq]  = bs;
                        hbs2[row * 4 + wq] = bs2;
                        hbk[row * 4 + wq]  = bk;
                    }
                }
            }
        }
        __syncthreads();

        // ---- combine quarters (ascending k ranges), final argmin + flagging ----
        if (t < ROWS_PER_BLOCK) {
            float bs = __int_as_float(0x7f800000), bs2 = bs;
            int   bk = 0;
            #pragma unroll
            for (int q = 0; q < 4; ++q) {
                float b  = hbs[t * 4 + q];
                int   k  = hbk[t * 4 + q];
                float s2 = hbs2[t * 4 + q];
                if (b < bs) { bs2 = bs; bs = b; bk = k; }
                else { bs2 = fminf(bs2, b); }
                bs2 = fminf(bs2, s2);
            }
            bestk[t] = bk;
            if (bs2 - bs < TAU) {
                int pos = atomicAdd(nflag, 1);
                flags[pos] = t;
            }
        }
        __syncthreads();

        // ---- exact recheck for flagged rows (rare): bit-exact reference math ----
        {
            int nf = *nflag;
            for (int i = warp; i < nf; i += 8) {
                int row = flags[i];
                const float* xg = inp + (size_t)(row0 + row) * DFULL + c * DSUB;
                // exact x2 in XLA order (lane-strided partials + shfl tree)
                float s = 0.0f;
                #pragma unroll
                for (int m = 0; m < 4; ++m) {
                    float v = xg[lane + 32 * m];
                    s = fmaf(v, v, s);
                }
                s = xla_warp_tree(s);
                float x2v = __shfl_sync(0xffffffffu, s, 0);
                float bs = __int_as_float(0x7f800000);
                int   bk = 0;
                #pragma unroll
                for (int kb = 0; kb < 4; ++kb) {
                    int k = kb * 32 + lane;
                    const float* eg = emb + ((size_t)c * KCODES + k) * DSUB;
                    float dt = 0.0f;
                    for (int dd = 0; dd < DSUB; ++dd)
                        dt = fmaf(xg[dd], eg[dd], dt);       // sequential, ascending
                    float sc = (x2v + e2s[k]) - 2.0f * dt;   // reference rounding
                    if (sc < bs) { bs = sc; bk = k; }        // lane ks ascending
                }
                #pragma unroll
                for (int off = 16; off >= 1; off >>= 1) {
                    float os = __shfl_xor_sync(0xffffffffu, bs, off);
                    int   ok = __shfl_xor_sync(0xffffffffu, bk, off);
                    if (os < bs || (os == bs && ok < bk)) { bs = os; bk = ok; }
                }
                if (lane == 0) bestk[row] = bk;
            }
        }
        __syncthreads();

        // ---- index accumulation + epilogue (quantized_sg, loss) from GLOBAL ----
        if (t < ROWS_PER_BLOCK) idxacc[t] += bestk[t] * powc;
        #pragma unroll
        for (int rr = 0; rr < ROWS_PER_BLOCK / 8; ++rr) {   // 8 rows per warp
            int r = warp * 8 + rr;
            int k = bestk[r];
            const float* eg = emb + ((size_t)c * KCODES + k) * DSUB;
            const float* xg = inp + (size_t)(row0 + r) * DFULL + c * DSUB;
            float* qrow = out_q + (size_t)(row0 + r) * DFULL + c * DSUB;

            float part = 0.0f;
            #pragma unroll
            for (int m = 0; m < 4; ++m) {
                int dd = lane + 32 * m;
                float ev = eg[dd];
                float xv = xg[dd];
                float dlt = ev - xv;
                part = fmaf(dlt, dlt, part);
                qrow[dd] = xv + dlt;                    // x + (q - x), matches ref
            }
            #pragma unroll
            for (int off = 16; off >= 1; off >>= 1)
                part += __shfl_xor_sync(0xffffffffu, part, off);
            if (lane == 0) lossacc[r] += part;
        }
        powc >>= 7;  // /128
        __syncthreads();
    }

    if (write_aux && t < ROWS_PER_BLOCK) {
        int n = row0 + t;
        out_idx[n] = (float)idxacc[t];
        float d2 = lossacc[t];
        out_loss[n] = d2 + 0.25f * d2;   // q_latent + 0.25*e_latent
    }
}

extern "C" void kernel_launch(void* const* d_in, const int* in_sizes, int n_in,
                              void* d_out, int out_size) {
    const float* inp = (const float*)d_in[0];   // inputs (64,2048,512) f32
    const float* emb = (const float*)d_in[1];   // embeddings (4,128,128) f32
    float* out = (float*)d_out;

    const long long QN = (long long)NROWS * DFULL;
    int write_aux = ((long long)out_size >= QN + 2LL * NROWS) ? 1 : 0;
    float* out_q    = out;
    float* out_idx  = out + QN;
    float* out_loss = out + QN + NROWS;

    pre_kernel<<<80, 256>>>(emb);

    cudaFuncSetAttribute(pvq_kernel,
                         cudaFuncAttributeMaxDynamicSharedMemorySize, SMEM_BYTES);
    pvq_kernel<<<NROWS / ROWS_PER_BLOCK, THREADS, SMEM_BYTES>>>(
        inp, emb, out_q, out_idx, out_loss, write_aux);
}